// round 1
// baseline (speedup 1.0000x reference)
#include <cuda_runtime.h>
#include <math_constants.h>

#define EPS 1e-5f
#define NMAX 100000

// Scratch: H2'[n][o] = sum_c relu(bn1(x@w1))[n][c] * conv_w[o][3+c]  +  p[n].Wxyz[o]
__device__ float g_H2[(size_t)NMAX * 64];

// ---------------------------------------------------------------------------
// Stage 1: per-point fused  x@w1 -> bn1 -> relu -> @W2^T (+ p.Wxyz)  -> g_H2
// Thread-per-point outer product; weights live in smem as [c][o] so the
// inner loads are warp-uniform LDS.128 broadcasts (1 phase each).
// ---------------------------------------------------------------------------
__global__ __launch_bounds__(128) void stage1_kernel(
    const float* __restrict__ p, const float* __restrict__ x,
    const float* __restrict__ w1,
    const float* __restrict__ g1, const float* __restrict__ b1,
    const float* __restrict__ m1, const float* __restrict__ v1,
    const float* __restrict__ conv_w, int N)
{
    __shared__ float w1s[64 * 64];   // [c][o]
    __shared__ float w2s[64 * 64];   // [c][o] = conv_w[o][3+c]
    __shared__ float s1s[64], t1s[64], wxs[64], wys[64], wzs[64];

    const int tid = threadIdx.x;
    for (int i = tid; i < 4096; i += 128) {
        w1s[i] = w1[i];
        int c = i >> 6, o = i & 63;
        w2s[i] = conv_w[o * 67 + 3 + c];
    }
    if (tid < 64) {
        float s = g1[tid] * rsqrtf(v1[tid] + EPS);
        s1s[tid] = s;
        t1s[tid] = b1[tid] - m1[tid] * s;
        wxs[tid] = conv_w[tid * 67 + 0];
        wys[tid] = conv_w[tid * 67 + 1];
        wzs[tid] = conv_w[tid * 67 + 2];
    }
    __syncthreads();

    const int n = blockIdx.x * 128 + tid;
    if (n >= N) return;

    float acc[64];
#pragma unroll
    for (int o = 0; o < 64; o++) acc[o] = 0.f;

    // matvec1: acc[o] = sum_c x[n][c] * w1[c][o]
    const float4* xrow = (const float4*)(x + (size_t)n * 64);
#pragma unroll
    for (int c4 = 0; c4 < 16; c4++) {
        float4 xv = xrow[c4];
        float xa[4] = {xv.x, xv.y, xv.z, xv.w};
#pragma unroll
        for (int u = 0; u < 4; u++) {
            float xc = xa[u];
            const float4* wr = (const float4*)&w1s[(c4 * 4 + u) * 64];
#pragma unroll
            for (int j = 0; j < 16; j++) {
                float4 w = wr[j];
                acc[4 * j + 0] = fmaf(xc, w.x, acc[4 * j + 0]);
                acc[4 * j + 1] = fmaf(xc, w.y, acc[4 * j + 1]);
                acc[4 * j + 2] = fmaf(xc, w.z, acc[4 * j + 2]);
                acc[4 * j + 3] = fmaf(xc, w.w, acc[4 * j + 3]);
            }
        }
    }

    // bn1 + relu -> h (registers)
    float h[64];
#pragma unroll
    for (int o = 0; o < 64; o++) {
        h[o] = fmaxf(fmaf(acc[o], s1s[o], t1s[o]), 0.f);
        acc[o] = 0.f;
    }

    // matvec2: acc[o] = sum_c h[c] * w2s[c][o]
#pragma unroll
    for (int c = 0; c < 64; c++) {
        float hc = h[c];
        const float4* wr = (const float4*)&w2s[c * 64];
#pragma unroll
        for (int j = 0; j < 16; j++) {
            float4 w = wr[j];
            acc[4 * j + 0] = fmaf(hc, w.x, acc[4 * j + 0]);
            acc[4 * j + 1] = fmaf(hc, w.y, acc[4 * j + 1]);
            acc[4 * j + 2] = fmaf(hc, w.z, acc[4 * j + 2]);
            acc[4 * j + 3] = fmaf(hc, w.w, acc[4 * j + 3]);
        }
    }

    // + p[n].Wxyz  (folds the "source side" of rel = p[m]-p[n] into H2)
    float px = p[(size_t)n * 3 + 0];
    float py = p[(size_t)n * 3 + 1];
    float pz = p[(size_t)n * 3 + 2];

    float4* outr = (float4*)(g_H2 + (size_t)n * 64);
#pragma unroll
    for (int j = 0; j < 16; j++) {
        float4 r;
        r.x = acc[4 * j + 0] + fmaf(px, wxs[4 * j + 0], fmaf(py, wys[4 * j + 0], pz * wzs[4 * j + 0]));
        r.y = acc[4 * j + 1] + fmaf(px, wxs[4 * j + 1], fmaf(py, wys[4 * j + 1], pz * wzs[4 * j + 1]));
        r.z = acc[4 * j + 2] + fmaf(px, wxs[4 * j + 2], fmaf(py, wys[4 * j + 2], pz * wzs[4 * j + 2]));
        r.w = acc[4 * j + 3] + fmaf(px, wxs[4 * j + 3], fmaf(py, wys[4 * j + 3], pz * wzs[4 * j + 3]));
        outr[j] = r;
    }
}

// ---------------------------------------------------------------------------
// Stage 2: warp-per-point.  Gather-max over the 16 neighbors (each H2 row
// read is a warp-uniform, fully-coalesced 256B load -> 2 L1tex wavefronts),
// subtract p[n].Wxyz, bn2+relu, matvec3 (f@w3), bn3 + residual + relu.
// ---------------------------------------------------------------------------
__global__ __launch_bounds__(256) void stage2_kernel(
    const float* __restrict__ p, const float* __restrict__ x,
    const int* __restrict__ idx, const float* __restrict__ conv_w,
    const float* __restrict__ g2, const float* __restrict__ b2,
    const float* __restrict__ m2, const float* __restrict__ v2,
    const float* __restrict__ w3,
    const float* __restrict__ g3, const float* __restrict__ b3,
    const float* __restrict__ m3, const float* __restrict__ v3,
    float* __restrict__ out, int N)
{
    __shared__ float w3s[64 * 64];   // [c][o]
    __shared__ float wxs[64], wys[64], wzs[64];
    __shared__ float s2s[64], t2s[64], s3s[64], t3s[64];
    __shared__ float fs[8][64];

    const int tid = threadIdx.x;
    for (int i = tid; i < 4096; i += 256) w3s[i] = w3[i];
    if (tid < 64) {
        wxs[tid] = conv_w[tid * 67 + 0];
        wys[tid] = conv_w[tid * 67 + 1];
        wzs[tid] = conv_w[tid * 67 + 2];
        float s2 = g2[tid] * rsqrtf(v2[tid] + EPS);
        s2s[tid] = s2;
        t2s[tid] = b2[tid] - m2[tid] * s2;
        float s3 = g3[tid] * rsqrtf(v3[tid] + EPS);
        s3s[tid] = s3;
        t3s[tid] = b3[tid] - m3[tid] * s3;
    }
    __syncthreads();

    const int w = tid >> 5;
    const int t = tid & 31;
    const int n = blockIdx.x * 8 + w;
    if (n >= N) return;

    const int o0 = 2 * t;

    // stash the 16 neighbor indices across lanes 0..15 once, shuffle per k
    int myidx = idx[(size_t)n * 16 + (t & 15)];

    float px = p[(size_t)n * 3 + 0];
    float py = p[(size_t)n * 3 + 1];
    float pz = p[(size_t)n * 3 + 2];
    float c0 = fmaf(px, wxs[o0 + 0], fmaf(py, wys[o0 + 0], pz * wzs[o0 + 0]));
    float c1 = fmaf(px, wxs[o0 + 1], fmaf(py, wys[o0 + 1], pz * wzs[o0 + 1]));

    float mv0 = -CUDART_INF_F, mv1 = -CUDART_INF_F;
#pragma unroll
    for (int k = 0; k < 16; k++) {
        int m = __shfl_sync(0xffffffffu, myidx, k);
        float2 v = *(const float2*)(g_H2 + (size_t)m * 64 + o0);
        mv0 = fmaxf(mv0, v.x);
        mv1 = fmaxf(mv1, v.y);
    }

    // bn2 + relu applied AFTER max (monotone since s2 > 0)
    float f0 = fmaxf(fmaf(mv0 - c0, s2s[o0 + 0], t2s[o0 + 0]), 0.f);
    float f1 = fmaxf(fmaf(mv1 - c1, s2s[o0 + 1], t2s[o0 + 1]), 0.f);
    fs[w][o0 + 0] = f0;
    fs[w][o0 + 1] = f1;
    __syncwarp();

    // matvec3: out_pre[o] = sum_c f[c] * w3[c][o]
    float a0 = 0.f, a1 = 0.f;
#pragma unroll
    for (int c = 0; c < 64; c++) {
        float fc = fs[w][c];
        float2 ww = *(const float2*)(w3s + c * 64 + o0);
        a0 = fmaf(fc, ww.x, a0);
        a1 = fmaf(fc, ww.y, a1);
    }

    float2 xv = *(const float2*)(x + (size_t)n * 64 + o0);
    float r0 = fmaxf(fmaf(a0, s3s[o0 + 0], t3s[o0 + 0]) + xv.x, 0.f);
    float r1 = fmaxf(fmaf(a1, s3s[o0 + 1], t3s[o0 + 1]) + xv.y, 0.f);
    *(float2*)(out + (size_t)n * 64 + o0) = make_float2(r0, r1);
}

extern "C" void kernel_launch(void* const* d_in, const int* in_sizes, int n_in,
                              void* d_out, int out_size)
{
    const float* p      = (const float*)d_in[0];
    const float* x      = (const float*)d_in[1];
    const int*   idx    = (const int*)  d_in[2];
    const float* w1     = (const float*)d_in[3];
    const float* g1     = (const float*)d_in[4];
    const float* b1     = (const float*)d_in[5];
    const float* m1     = (const float*)d_in[6];
    const float* v1     = (const float*)d_in[7];
    const float* conv_w = (const float*)d_in[8];
    const float* g2     = (const float*)d_in[9];
    const float* b2     = (const float*)d_in[10];
    const float* m2     = (const float*)d_in[11];
    const float* v2     = (const float*)d_in[12];
    const float* w3     = (const float*)d_in[13];
    const float* g3     = (const float*)d_in[14];
    const float* b3     = (const float*)d_in[15];
    const float* m3     = (const float*)d_in[16];
    const float* v3     = (const float*)d_in[17];
    float* out = (float*)d_out;

    const int N = in_sizes[0] / 3;

    stage1_kernel<<<(N + 127) / 128, 128>>>(p, x, w1, g1, b1, m1, v1, conv_w, N);
    stage2_kernel<<<(N + 7) / 8, 256>>>(p, x, idx, conv_w,
                                        g2, b2, m2, v2, w3, g3, b3, m3, v3,
                                        out, N);
}

// round 2
// speedup vs baseline: 1.6997x; 1.6997x over previous
#include <cuda_runtime.h>
#include <cuda_fp16.h>
#include <math_constants.h>

#define EPS 1e-5f
#define NMAX 100000
typedef unsigned long long ull;

// Packed f32x2 helpers (sm_100+ PTX; ptxas never auto-fuses FFMA2)
#define FMA2(d, a, b, c) \
    asm("fma.rn.f32x2 %0, %1, %2, %3;" : "=l"(d) : "l"(a), "l"(b), "l"(c))

__device__ __forceinline__ ull pk2(float lo, float hi) {
    ull r; asm("mov.b64 %0, {%1, %2};" : "=l"(r) : "f"(lo), "f"(hi)); return r;
}
__device__ __forceinline__ float2 upk2(ull v) {
    float2 r; asm("mov.b64 {%0, %1}, %2;" : "=f"(r.x), "=f"(r.y) : "l"(v)); return r;
}

// Gather table: H2'[n][o] = (relu(bn1(x@w1)) @ W2^T)[n][o] + p[n].Wxyz[o], fp16.
// Row = 64 halves = 128 B (one L1 wavefront per warp-uniform gather).
__device__ __half2 g_H2[(size_t)NMAX * 32];

// ---------------------------------------------------------------------------
// Stage 1: thread-per-point  x@w1 -> bn1 -> relu -> @W2^T (+ p.Wxyz) -> fp16
// All FMAs are packed f32x2 (pairs of adjacent outputs).
// ---------------------------------------------------------------------------
__global__ __launch_bounds__(128) void stage1_kernel(
    const float* __restrict__ p, const float* __restrict__ x,
    const float* __restrict__ w1,
    const float* __restrict__ g1, const float* __restrict__ b1,
    const float* __restrict__ m1, const float* __restrict__ v1,
    const float* __restrict__ conv_w, int N)
{
    __shared__ __align__(16) float w1s[64 * 64];   // [c][o]
    __shared__ __align__(16) float w2s[64 * 64];   // [c][o] = conv_w[o][3+c]
    __shared__ float s1s[64], t1s[64], wxs[64], wys[64], wzs[64];

    const int tid = threadIdx.x;
    for (int i = tid; i < 4096; i += 128) {
        w1s[i] = w1[i];
        int c = i >> 6, o = i & 63;
        w2s[i] = conv_w[o * 67 + 3 + c];
    }
    if (tid < 64) {
        float s = g1[tid] * rsqrtf(v1[tid] + EPS);
        s1s[tid] = s;
        t1s[tid] = b1[tid] - m1[tid] * s;
        wxs[tid] = conv_w[tid * 67 + 0];
        wys[tid] = conv_w[tid * 67 + 1];
        wzs[tid] = conv_w[tid * 67 + 2];
    }
    __syncthreads();

    const int n = blockIdx.x * 128 + tid;
    if (n >= N) return;

    ull acc[32];
#pragma unroll
    for (int j = 0; j < 32; j++) acc[j] = 0ull;

    // matvec1: acc pairs over o; per c one packed multiplier
    const float4* xrow = (const float4*)(x + (size_t)n * 64);
#pragma unroll
    for (int c4 = 0; c4 < 16; c4++) {
        float4 xv = xrow[c4];
        float xa[4] = {xv.x, xv.y, xv.z, xv.w};
#pragma unroll
        for (int u = 0; u < 4; u++) {
            ull xc = pk2(xa[u], xa[u]);
            const ulonglong2* wr = (const ulonglong2*)&w1s[(c4 * 4 + u) * 64];
#pragma unroll
            for (int j = 0; j < 16; j++) {
                ulonglong2 w = wr[j];
                FMA2(acc[2 * j + 0], xc, w.x, acc[2 * j + 0]);
                FMA2(acc[2 * j + 1], xc, w.y, acc[2 * j + 1]);
            }
        }
    }

    // bn1 + relu -> h (scalar, needed as per-channel multipliers next)
    float h[64];
#pragma unroll
    for (int j = 0; j < 32; j++) {
        float2 a = upk2(acc[j]);
        h[2 * j + 0] = fmaxf(fmaf(a.x, s1s[2 * j + 0], t1s[2 * j + 0]), 0.f);
        h[2 * j + 1] = fmaxf(fmaf(a.y, s1s[2 * j + 1], t1s[2 * j + 1]), 0.f);
        acc[j] = 0ull;
    }

    // matvec2: acc[o] = sum_c h[c] * w2s[c][o]
#pragma unroll
    for (int c = 0; c < 64; c++) {
        ull hc = pk2(h[c], h[c]);
        const ulonglong2* wr = (const ulonglong2*)&w2s[c * 64];
#pragma unroll
        for (int j = 0; j < 16; j++) {
            ulonglong2 w = wr[j];
            FMA2(acc[2 * j + 0], hc, w.x, acc[2 * j + 0]);
            FMA2(acc[2 * j + 1], hc, w.y, acc[2 * j + 1]);
        }
    }

    // + p[n].Wxyz, convert to fp16, store 128B row
    float px = p[(size_t)n * 3 + 0];
    float py = p[(size_t)n * 3 + 1];
    float pz = p[(size_t)n * 3 + 2];

    __half2 hout[32];
#pragma unroll
    for (int j = 0; j < 32; j++) {
        float2 a = upk2(acc[j]);
        int o = 2 * j;
        float r0 = a.x + fmaf(px, wxs[o + 0], fmaf(py, wys[o + 0], pz * wzs[o + 0]));
        float r1 = a.y + fmaf(px, wxs[o + 1], fmaf(py, wys[o + 1], pz * wzs[o + 1]));
        hout[j] = __floats2half2_rn(r0, r1);
    }
    uint4* dst = (uint4*)(g_H2 + (size_t)n * 32);
    const uint4* src = (const uint4*)hout;
#pragma unroll
    for (int q = 0; q < 8; q++) dst[q] = src[q];
}

// ---------------------------------------------------------------------------
// Stage 2: warp-per-8-points. Phase A: fp16 gather-max (1 wavefront/row),
// bn2+relu (monotone, applied after max), f stored pre-packed (both f32x2
// halves) in smem. Phase B: matvec3 with w3 pair loaded ONCE per c for all
// 8 points (8x smem-byte amortization), packed FFMA2. bn3 + residual + relu.
// ---------------------------------------------------------------------------
__global__ __launch_bounds__(256) void stage2_kernel(
    const float* __restrict__ p, const float* __restrict__ x,
    const int* __restrict__ idx, const float* __restrict__ conv_w,
    const float* __restrict__ g2, const float* __restrict__ b2,
    const float* __restrict__ m2, const float* __restrict__ v2,
    const float* __restrict__ w3,
    const float* __restrict__ g3, const float* __restrict__ b3,
    const float* __restrict__ m3, const float* __restrict__ v3,
    float* __restrict__ out, int N)
{
    __shared__ __align__(16) float w3s[64 * 64];        // [c][o]
    __shared__ __align__(16) ull fspk[64][64];          // [pt_local][c], both halves = f
    __shared__ float wxs[64], wys[64], wzs[64];
    __shared__ float s2s[64], t2s[64], s3s[64], t3s[64];

    const int tid = threadIdx.x;
    for (int i = tid; i < 4096; i += 256) w3s[i] = w3[i];
    if (tid < 64) {
        wxs[tid] = conv_w[tid * 67 + 0];
        wys[tid] = conv_w[tid * 67 + 1];
        wzs[tid] = conv_w[tid * 67 + 2];
        float s2 = g2[tid] * rsqrtf(v2[tid] + EPS);
        s2s[tid] = s2;
        t2s[tid] = b2[tid] - m2[tid] * s2;
        float s3 = g3[tid] * rsqrtf(v3[tid] + EPS);
        s3s[tid] = s3;
        t3s[tid] = b3[tid] - m3[tid] * s3;
    }
    __syncthreads();

    const int w = tid >> 5;
    const int t = tid & 31;
    const int n0 = blockIdx.x * 64 + w * 8;   // this warp's 8-point group
    if (n0 >= N) return;                       // N % 8 == 0: group all-valid

    const int o0 = 2 * t;
    const float sb20 = s2s[o0], sb21 = s2s[o0 + 1];
    const float tb20 = t2s[o0], tb21 = t2s[o0 + 1];
    const float wx0 = wxs[o0], wx1 = wxs[o0 + 1];
    const float wy0 = wys[o0], wy1 = wys[o0 + 1];
    const float wz0 = wzs[o0], wz1 = wzs[o0 + 1];

    // 128 neighbor indices for the group, coalesced into 4 regs/lane
    const int* ib = idx + (size_t)n0 * 16;
    int i0 = ib[t], i1 = ib[32 + t], i2 = ib[64 + t], i3 = ib[96 + t];

    const int pl0 = w * 8;

    // ---- Phase A: gather-max + bn2 + relu per point ----
#pragma unroll
    for (int pt = 0; pt < 8; pt++) {
        const int n = n0 + pt;
        float px = p[(size_t)n * 3 + 0];
        float py = p[(size_t)n * 3 + 1];
        float pz = p[(size_t)n * 3 + 2];
        float c0 = fmaf(px, wx0, fmaf(py, wy0, pz * wz0));
        float c1 = fmaf(px, wx1, fmaf(py, wy1, pz * wz1));

        __half2 mv = __float2half2_rn(-CUDART_INF_F);
#pragma unroll
        for (int k = 0; k < 16; k++) {
            const int s = pt * 16 + k;
            int v = (s < 32) ? i0 : (s < 64) ? i1 : (s < 96) ? i2 : i3;
            int m = __shfl_sync(0xffffffffu, v, s & 31);
            mv = __hmax2(mv, g_H2[(size_t)m * 32 + t]);
        }
        float2 mf = __half22float2(mv);
        float f0 = fmaxf(fmaf(mf.x - c0, sb20, tb20), 0.f);
        float f1 = fmaxf(fmaf(mf.y - c1, sb21, tb21), 0.f);
        ulonglong2 st;
        st.x = pk2(f0, f0);
        st.y = pk2(f1, f1);
        *(ulonglong2*)&fspk[pl0 + pt][o0] = st;
    }
    __syncwarp();

    // ---- Phase B: matvec3 for 8 points, weight pair loaded once per c ----
    ull a[8];
#pragma unroll
    for (int pt = 0; pt < 8; pt++) a[pt] = 0ull;

    const ull* w3u = (const ull*)w3s;
#pragma unroll 8
    for (int c = 0; c < 64; c++) {
        ull wp = w3u[c * 32 + t];
#pragma unroll
        for (int pt = 0; pt < 8; pt++) {
            ull fv = fspk[pl0 + pt][c];
            FMA2(a[pt], fv, wp, a[pt]);
        }
    }

    // ---- epilogue: bn3 + residual + relu ----
    const float sb30 = s3s[o0], sb31 = s3s[o0 + 1];
    const float tb30 = t3s[o0], tb31 = t3s[o0 + 1];
#pragma unroll
    for (int pt = 0; pt < 8; pt++) {
        const int n = n0 + pt;
        float2 av = upk2(a[pt]);
        float2 xv = *(const float2*)(x + (size_t)n * 64 + o0);
        float r0 = fmaxf(fmaf(av.x, sb30, tb30) + xv.x, 0.f);
        float r1 = fmaxf(fmaf(av.y, sb31, tb31) + xv.y, 0.f);
        *(float2*)(out + (size_t)n * 64 + o0) = make_float2(r0, r1);
    }
}

extern "C" void kernel_launch(void* const* d_in, const int* in_sizes, int n_in,
                              void* d_out, int out_size)
{
    const float* p      = (const float*)d_in[0];
    const float* x      = (const float*)d_in[1];
    const int*   idx    = (const int*)  d_in[2];
    const float* w1     = (const float*)d_in[3];
    const float* g1     = (const float*)d_in[4];
    const float* b1     = (const float*)d_in[5];
    const float* m1     = (const float*)d_in[6];
    const float* v1     = (const float*)d_in[7];
    const float* conv_w = (const float*)d_in[8];
    const float* g2     = (const float*)d_in[9];
    const float* b2     = (const float*)d_in[10];
    const float* m2     = (const float*)d_in[11];
    const float* v2     = (const float*)d_in[12];
    const float* w3     = (const float*)d_in[13];
    const float* g3     = (const float*)d_in[14];
    const float* b3     = (const float*)d_in[15];
    const float* m3     = (const float*)d_in[16];
    const float* v3     = (const float*)d_in[17];
    float* out = (float*)d_out;

    const int N = in_sizes[0] / 3;

    stage1_kernel<<<(N + 127) / 128, 128>>>(p, x, w1, g1, b1, m1, v1, conv_w, N);
    stage2_kernel<<<(N + 63) / 64, 256>>>(p, x, idx, conv_w,
                                          g2, b2, m2, v2, w3, g3, b3, m3, v3,
                                          out, N);
}

// round 3
// speedup vs baseline: 1.7075x; 1.0046x over previous
#include <cuda_runtime.h>
#include <cuda_fp16.h>
#include <math_constants.h>

#define EPS 1e-5f
#define NMAX 100000
typedef unsigned long long ull;

// Packed f32x2 helpers (sm_100+ PTX; ptxas never auto-fuses FFMA2)
#define FMA2(d, a, b, c) \
    asm("fma.rn.f32x2 %0, %1, %2, %3;" : "=l"(d) : "l"(a), "l"(b), "l"(c))

__device__ __forceinline__ ull pk2(float lo, float hi) {
    ull r; asm("mov.b64 %0, {%1, %2};" : "=l"(r) : "f"(lo), "f"(hi)); return r;
}
__device__ __forceinline__ float2 upk2(ull v) {
    float2 r; asm("mov.b64 {%0, %1}, %2;" : "=f"(r.x), "=f"(r.y) : "l"(v)); return r;
}

// Gather table: H2'[n][o] = (relu(bn1(x@w1)) @ W2^T)[n][o] + p[n].Wxyz[o], fp16.
// Row = 64 halves = 128 B (one L1 wavefront per warp-uniform gather).
__device__ __half2 g_H2[(size_t)NMAX * 32];

// ---------------------------------------------------------------------------
// Stage 1: thread-per-point  x@w1 -> bn1 -> relu -> @W2^T (+ p.Wxyz) -> fp16
// All FMAs are packed f32x2 (pairs of adjacent outputs). (Unchanged from R2.)
// ---------------------------------------------------------------------------
__global__ __launch_bounds__(128) void stage1_kernel(
    const float* __restrict__ p, const float* __restrict__ x,
    const float* __restrict__ w1,
    const float* __restrict__ g1, const float* __restrict__ b1,
    const float* __restrict__ m1, const float* __restrict__ v1,
    const float* __restrict__ conv_w, int N)
{
    __shared__ __align__(16) float w1s[64 * 64];   // [c][o]
    __shared__ __align__(16) float w2s[64 * 64];   // [c][o] = conv_w[o][3+c]
    __shared__ float s1s[64], t1s[64], wxs[64], wys[64], wzs[64];

    const int tid = threadIdx.x;
    for (int i = tid; i < 4096; i += 128) {
        w1s[i] = w1[i];
        int c = i >> 6, o = i & 63;
        w2s[i] = conv_w[o * 67 + 3 + c];
    }
    if (tid < 64) {
        float s = g1[tid] * rsqrtf(v1[tid] + EPS);
        s1s[tid] = s;
        t1s[tid] = b1[tid] - m1[tid] * s;
        wxs[tid] = conv_w[tid * 67 + 0];
        wys[tid] = conv_w[tid * 67 + 1];
        wzs[tid] = conv_w[tid * 67 + 2];
    }
    __syncthreads();

    const int n = blockIdx.x * 128 + tid;
    if (n >= N) return;

    ull acc[32];
#pragma unroll
    for (int j = 0; j < 32; j++) acc[j] = 0ull;

    // matvec1: acc pairs over o; per c one packed multiplier
    const float4* xrow = (const float4*)(x + (size_t)n * 64);
#pragma unroll
    for (int c4 = 0; c4 < 16; c4++) {
        float4 xv = xrow[c4];
        float xa[4] = {xv.x, xv.y, xv.z, xv.w};
#pragma unroll
        for (int u = 0; u < 4; u++) {
            ull xc = pk2(xa[u], xa[u]);
            const ulonglong2* wr = (const ulonglong2*)&w1s[(c4 * 4 + u) * 64];
#pragma unroll
            for (int j = 0; j < 16; j++) {
                ulonglong2 w = wr[j];
                FMA2(acc[2 * j + 0], xc, w.x, acc[2 * j + 0]);
                FMA2(acc[2 * j + 1], xc, w.y, acc[2 * j + 1]);
            }
        }
    }

    // bn1 + relu -> h (scalar, needed as per-channel multipliers next)
    float h[64];
#pragma unroll
    for (int j = 0; j < 32; j++) {
        float2 a = upk2(acc[j]);
        h[2 * j + 0] = fmaxf(fmaf(a.x, s1s[2 * j + 0], t1s[2 * j + 0]), 0.f);
        h[2 * j + 1] = fmaxf(fmaf(a.y, s1s[2 * j + 1], t1s[2 * j + 1]), 0.f);
        acc[j] = 0ull;
    }

    // matvec2: acc[o] = sum_c h[c] * w2s[c][o]
#pragma unroll
    for (int c = 0; c < 64; c++) {
        ull hc = pk2(h[c], h[c]);
        const ulonglong2* wr = (const ulonglong2*)&w2s[c * 64];
#pragma unroll
        for (int j = 0; j < 16; j++) {
            ulonglong2 w = wr[j];
            FMA2(acc[2 * j + 0], hc, w.x, acc[2 * j + 0]);
            FMA2(acc[2 * j + 1], hc, w.y, acc[2 * j + 1]);
        }
    }

    // + p[n].Wxyz, convert to fp16, store 128B row
    float px = p[(size_t)n * 3 + 0];
    float py = p[(size_t)n * 3 + 1];
    float pz = p[(size_t)n * 3 + 2];

    __half2 hout[32];
#pragma unroll
    for (int j = 0; j < 32; j++) {
        float2 a = upk2(acc[j]);
        int o = 2 * j;
        float r0 = a.x + fmaf(px, wxs[o + 0], fmaf(py, wys[o + 0], pz * wzs[o + 0]));
        float r1 = a.y + fmaf(px, wxs[o + 1], fmaf(py, wys[o + 1], pz * wzs[o + 1]));
        hout[j] = __floats2half2_rn(r0, r1);
    }
    uint4* dst = (uint4*)(g_H2 + (size_t)n * 32);
    const uint4* src = (const uint4*)hout;
#pragma unroll
    for (int q = 0; q < 8; q++) dst[q] = src[q];
}

// ---------------------------------------------------------------------------
// Stage 2: warp-per-8-points.
// Phase A: fp16 gather-max (1 wavefront/row), bn2+relu after max (monotone),
//          f stored pre-packed (both f32x2 halves) in smem, contiguous in c.
// Phase B: paired-c matvec3: one LDS.128 delivers the w3 pairs for channels
//          (c,c+1) per lane; one broadcast LDS.128 delivers f[pt][c..c+1].
//          640 -> 384 L1 wavefronts per warp vs R2.
// ---------------------------------------------------------------------------
__global__ __launch_bounds__(256, 4) void stage2_kernel(
    const float* __restrict__ p, const float* __restrict__ x,
    const int* __restrict__ idx, const float* __restrict__ conv_w,
    const float* __restrict__ g2, const float* __restrict__ b2,
    const float* __restrict__ m2, const float* __restrict__ v2,
    const float* __restrict__ w3,
    const float* __restrict__ g3, const float* __restrict__ b3,
    const float* __restrict__ m3, const float* __restrict__ v3,
    float* __restrict__ out, int N)
{
    // w3r[c2][lane] = { pk(w3[2c2][2t], w3[2c2][2t+1]), pk(w3[2c2+1][2t], w3[2c2+1][2t+1]) }
    __shared__ __align__(16) ulonglong2 w3r[32 * 32];   // 16 KB
    __shared__ __align__(16) ull fspk[64][64];          // 32 KB: [pt_local][c], dup halves
    __shared__ float wxs[64], wys[64], wzs[64];
    __shared__ float s2s[64], t2s[64], s3s[64], t3s[64];

    const int tid = threadIdx.x;
    // build repacked w3: entry e = c2*32 + lane
    for (int e = tid; e < 1024; e += 256) {
        int c2 = e >> 5, l = e & 31;
        int c = 2 * c2, o = 2 * l;
        ulonglong2 v;
        v.x = pk2(w3[c * 64 + o], w3[c * 64 + o + 1]);
        v.y = pk2(w3[(c + 1) * 64 + o], w3[(c + 1) * 64 + o + 1]);
        w3r[e] = v;
    }
    if (tid < 64) {
        wxs[tid] = conv_w[tid * 67 + 0];
        wys[tid] = conv_w[tid * 67 + 1];
        wzs[tid] = conv_w[tid * 67 + 2];
        float s2 = g2[tid] * rsqrtf(v2[tid] + EPS);
        s2s[tid] = s2;
        t2s[tid] = b2[tid] - m2[tid] * s2;
        float s3 = g3[tid] * rsqrtf(v3[tid] + EPS);
        s3s[tid] = s3;
        t3s[tid] = b3[tid] - m3[tid] * s3;
    }
    __syncthreads();

    const int w = tid >> 5;
    const int t = tid & 31;
    const int n0 = blockIdx.x * 64 + w * 8;   // this warp's 8-point group
    if (n0 >= N) return;                      // N % 8 == 0: group all-valid

    const int o0 = 2 * t;
    const int pl0 = w * 8;

    // 128 neighbor indices for the group, coalesced into 4 regs/lane
    const int* ib = idx + (size_t)n0 * 16;
    int i0 = ib[t], i1 = ib[32 + t], i2 = ib[64 + t], i3 = ib[96 + t];

    // ---- Phase A: gather-max + bn2 + relu per point ----
    {
        const float sb20 = s2s[o0], sb21 = s2s[o0 + 1];
        const float tb20 = t2s[o0], tb21 = t2s[o0 + 1];
        const float wx0 = wxs[o0], wx1 = wxs[o0 + 1];
        const float wy0 = wys[o0], wy1 = wys[o0 + 1];
        const float wz0 = wzs[o0], wz1 = wzs[o0 + 1];
#pragma unroll
        for (int pt = 0; pt < 8; pt++) {
            const int n = n0 + pt;
            float px = p[(size_t)n * 3 + 0];
            float py = p[(size_t)n * 3 + 1];
            float pz = p[(size_t)n * 3 + 2];
            float c0 = fmaf(px, wx0, fmaf(py, wy0, pz * wz0));
            float c1 = fmaf(px, wx1, fmaf(py, wy1, pz * wz1));

            __half2 mv = __float2half2_rn(-CUDART_INF_F);
#pragma unroll
            for (int k = 0; k < 16; k++) {
                const int s = pt * 16 + k;
                int v = (s < 32) ? i0 : (s < 64) ? i1 : (s < 96) ? i2 : i3;
                int m = __shfl_sync(0xffffffffu, v, s & 31);
                mv = __hmax2(mv, g_H2[(size_t)m * 32 + t]);
            }
            float2 mf = __half22float2(mv);
            float f0 = fmaxf(fmaf(mf.x - c0, sb20, tb20), 0.f);
            float f1 = fmaxf(fmaf(mf.y - c1, sb21, tb21), 0.f);
            ulonglong2 st;
            st.x = pk2(f0, f0);
            st.y = pk2(f1, f1);
            *(ulonglong2*)&fspk[pl0 + pt][o0] = st;
        }
    }
    __syncwarp();

    // ---- Phase B: paired-c matvec3 for 8 points ----
    ull a[8];
#pragma unroll
    for (int pt = 0; pt < 8; pt++) a[pt] = 0ull;

#pragma unroll
    for (int c2 = 0; c2 < 32; c2++) {
        ulonglong2 wp = w3r[c2 * 32 + t];
#pragma unroll
        for (int pt = 0; pt < 8; pt++) {
            ulonglong2 fv = *(const ulonglong2*)&fspk[pl0 + pt][2 * c2];
            FMA2(a[pt], fv.x, wp.x, a[pt]);
            FMA2(a[pt], fv.y, wp.y, a[pt]);
        }
    }

    // ---- epilogue: bn3 + residual + relu (constants re-read from smem) ----
    const float sb30 = s3s[o0], sb31 = s3s[o0 + 1];
    const float tb30 = t3s[o0], tb31 = t3s[o0 + 1];
#pragma unroll
    for (int pt = 0; pt < 8; pt++) {
        const int n = n0 + pt;
        float2 av = upk2(a[pt]);
        float2 xv = *(const float2*)(x + (size_t)n * 64 + o0);
        float r0 = fmaxf(fmaf(av.x, sb30, tb30) + xv.x, 0.f);
        float r1 = fmaxf(fmaf(av.y, sb31, tb31) + xv.y, 0.f);
        *(float2*)(out + (size_t)n * 64 + o0) = make_float2(r0, r1);
    }
}

extern "C" void kernel_launch(void* const* d_in, const int* in_sizes, int n_in,
                              void* d_out, int out_size)
{
    const float* p      = (const float*)d_in[0];
    const float* x      = (const float*)d_in[1];
    const int*   idx    = (const int*)  d_in[2];
    const float* w1     = (const float*)d_in[3];
    const float* g1     = (const float*)d_in[4];
    const float* b1     = (const float*)d_in[5];
    const float* m1     = (const float*)d_in[6];
    const float* v1     = (const float*)d_in[7];
    const float* conv_w = (const float*)d_in[8];
    const float* g2     = (const float*)d_in[9];
    const float* b2     = (const float*)d_in[10];
    const float* m2     = (const float*)d_in[11];
    const float* v2     = (const float*)d_in[12];
    const float* w3     = (const float*)d_in[13];
    const float* g3     = (const float*)d_in[14];
    const float* b3     = (const float*)d_in[15];
    const float* m3     = (const float*)d_in[16];
    const float* v3     = (const float*)d_in[17];
    float* out = (float*)d_out;

    const int N = in_sizes[0] / 3;

    stage1_kernel<<<(N + 127) / 128, 128>>>(p, x, w1, g1, b1, m1, v1, conv_w, N);
    stage2_kernel<<<(N + 63) / 64, 256>>>(p, x, idx, conv_w,
                                          g2, b2, m2, v2, w3, g3, b3, m3, v3,
                                          out, N);
}

// round 4
// speedup vs baseline: 2.0821x; 1.2193x over previous
#include <cuda_runtime.h>
#include <cuda_fp16.h>
#include <math_constants.h>

#define EPS 1e-5f
#define NMAX 100000
typedef unsigned long long ull;

// Packed f32x2 helpers (sm_100+ PTX; ptxas never auto-fuses FFMA2)
#define FMA2(d, a, b, c) \
    asm("fma.rn.f32x2 %0, %1, %2, %3;" : "=l"(d) : "l"(a), "l"(b), "l"(c))

__device__ __forceinline__ ull pk2(float lo, float hi) {
    ull r; asm("mov.b64 %0, {%1, %2};" : "=l"(r) : "f"(lo), "f"(hi)); return r;
}
__device__ __forceinline__ float2 upk2(ull v) {
    float2 r; asm("mov.b64 {%0, %1}, %2;" : "=f"(r.x), "=f"(r.y) : "l"(v)); return r;
}

// Gather table: H2'[n][o] = (relu(bn1(x@w1)) @ W2^T)[n][o] + p[n].Wxyz[o], fp16.
// Row = 64 halves = 128 B (one L1 wavefront per warp-uniform gather).
__device__ __half2 g_H2[(size_t)NMAX * 32];

// ---------------------------------------------------------------------------
// Stage 1 (rewritten): block-cooperative chained GEMMs.
// Block = 128 points x 64 outs, K=64. 128 threads, thread tile = 8pt x 8out.
// GEMM1: xs @ w1 -> bn1+relu -> h (written back into xs) -> GEMM2: h @ w2^T
// -> + p.Wxyz -> fp16 g_H2.
// Dynamic smem: xs[128][72] | w1s[64][64] | w2s[64][68] | consts.
// ---------------------------------------------------------------------------
#define XS_PITCH 72
#define W2_PITCH 68
#define S1_OFF_XS   0
#define S1_OFF_W1   (128 * XS_PITCH)                 // 9216
#define S1_OFF_W2   (S1_OFF_W1 + 64 * 64)            // 13312
#define S1_OFF_CST  (S1_OFF_W2 + 64 * W2_PITCH)      // 17664
#define S1_SMEM_FLOATS (S1_OFF_CST + 5 * 64)         // 17984
#define S1_SMEM_BYTES  (S1_SMEM_FLOATS * 4)          // 71936

__global__ __launch_bounds__(128, 3) void stage1_kernel(
    const float* __restrict__ p, const float* __restrict__ x,
    const float* __restrict__ w1,
    const float* __restrict__ g1, const float* __restrict__ b1,
    const float* __restrict__ m1, const float* __restrict__ v1,
    const float* __restrict__ conv_w, int N)
{
    extern __shared__ float smem[];
    float* xs  = smem + S1_OFF_XS;     // [128][72]
    float* w1s = smem + S1_OFF_W1;     // [64][64]  (= w1 layout [c][o])
    float* w2s = smem + S1_OFF_W2;     // [64][68]  ([c][o] = conv_w[o][3+c])
    float* s1s = smem + S1_OFF_CST;
    float* t1s = s1s + 64;
    float* wxs = s1s + 128;
    float* wys = s1s + 192;
    float* wzs = s1s + 256;

    const int tid = threadIdx.x;
    const int n0  = blockIdx.x * 128;

    // ---- loaders ----
    const float4* xg = (const float4*)x;
#pragma unroll
    for (int it = 0; it < 16; it++) {
        int e  = tid + it * 128;          // 2048 float4 = 128x64 floats
        int pt = e >> 4, c4 = e & 15;
        int n  = n0 + pt;
        float4 v = make_float4(0.f, 0.f, 0.f, 0.f);
        if (n < N) v = xg[(size_t)n * 16 + c4];
        *(float4*)&xs[pt * XS_PITCH + c4 * 4] = v;
    }
    const float4* w1g = (const float4*)w1;
#pragma unroll
    for (int it = 0; it < 8; it++) {
        int j = tid + it * 128;
        *(float4*)&w1s[j * 4] = w1g[j];
    }
    // w2s: coalesced read of conv_w, scattered (padded-pitch) STS
#pragma unroll
    for (int it = 0; it < 34; it++) {
        int i = tid + it * 128;
        if (i < 64 * 67) {
            int o = i / 67, r = i % 67;
            float v = conv_w[i];
            if (r >= 3) w2s[(r - 3) * W2_PITCH + o] = v;
        }
    }
    if (tid < 64) {
        float s = g1[tid] * rsqrtf(v1[tid] + EPS);
        s1s[tid] = s;
        t1s[tid] = b1[tid] - m1[tid] * s;
        wxs[tid] = conv_w[tid * 67 + 0];
        wys[tid] = conv_w[tid * 67 + 1];
        wzs[tid] = conv_w[tid * 67 + 2];
    }
    __syncthreads();

    const int oo = tid & 7;        // out-group: outs 8oo..8oo+7
    const int po = tid & 0x78 ? (tid >> 3) : (tid >> 3);  // 0..15
    const int ob = oo * 8;

    ull acc[8][4];
#pragma unroll
    for (int i = 0; i < 8; i++)
#pragma unroll
        for (int j = 0; j < 4; j++) acc[i][j] = 0ull;

    // ---- GEMM1: acc[pt][o] = sum_k xs[pt][k] * w1s[k][o] ----
#pragma unroll
    for (int k4 = 0; k4 < 16; k4++) {
        float4 xv[8];
#pragma unroll
        for (int i = 0; i < 8; i++)
            xv[i] = *(const float4*)&xs[(po + 16 * i) * XS_PITCH + k4 * 4];
#pragma unroll
        for (int kk = 0; kk < 4; kk++) {
            int k = k4 * 4 + kk;
            ulonglong2 wa = *(const ulonglong2*)&w1s[k * 64 + ob];
            ulonglong2 wb = *(const ulonglong2*)&w1s[k * 64 + ob + 4];
#pragma unroll
            for (int i = 0; i < 8; i++) {
                float xc = (kk == 0) ? xv[i].x : (kk == 1) ? xv[i].y
                         : (kk == 2) ? xv[i].z : xv[i].w;
                ull xd = pk2(xc, xc);
                FMA2(acc[i][0], xd, wa.x, acc[i][0]);
                FMA2(acc[i][1], xd, wa.y, acc[i][1]);
                FMA2(acc[i][2], xd, wb.x, acc[i][2]);
                FMA2(acc[i][3], xd, wb.y, acc[i][3]);
            }
        }
    }
    __syncthreads();   // all GEMM1 reads of xs complete

    // ---- bn1 + relu, write h back into xs ----
#pragma unroll
    for (int i = 0; i < 8; i++) {
        float hv[8];
#pragma unroll
        for (int j = 0; j < 4; j++) {
            float2 a = upk2(acc[i][j]);
            int o = ob + 2 * j;
            hv[2 * j + 0] = fmaxf(fmaf(a.x, s1s[o + 0], t1s[o + 0]), 0.f);
            hv[2 * j + 1] = fmaxf(fmaf(a.y, s1s[o + 1], t1s[o + 1]), 0.f);
            acc[i][j] = 0ull;
        }
        float* row = &xs[(po + 16 * i) * XS_PITCH + ob];
        *(float4*)(row)     = make_float4(hv[0], hv[1], hv[2], hv[3]);
        *(float4*)(row + 4) = make_float4(hv[4], hv[5], hv[6], hv[7]);
    }
    __syncthreads();

    // ---- GEMM2: acc[pt][o] = sum_k h[pt][k] * w2s[k][o] ----
#pragma unroll
    for (int k4 = 0; k4 < 16; k4++) {
        float4 xv[8];
#pragma unroll
        for (int i = 0; i < 8; i++)
            xv[i] = *(const float4*)&xs[(po + 16 * i) * XS_PITCH + k4 * 4];
#pragma unroll
        for (int kk = 0; kk < 4; kk++) {
            int k = k4 * 4 + kk;
            ulonglong2 wa = *(const ulonglong2*)&w2s[k * W2_PITCH + ob];
            ulonglong2 wb = *(const ulonglong2*)&w2s[k * W2_PITCH + ob + 4];
#pragma unroll
            for (int i = 0; i < 8; i++) {
                float xc = (kk == 0) ? xv[i].x : (kk == 1) ? xv[i].y
                         : (kk == 2) ? xv[i].z : xv[i].w;
                ull xd = pk2(xc, xc);
                FMA2(acc[i][0], xd, wa.x, acc[i][0]);
                FMA2(acc[i][1], xd, wa.y, acc[i][1]);
                FMA2(acc[i][2], xd, wb.x, acc[i][2]);
                FMA2(acc[i][3], xd, wb.y, acc[i][3]);
            }
        }
    }

    // ---- epilogue: + p[n].Wxyz, fp16 pack, store g_H2 ----
#pragma unroll
    for (int i = 0; i < 8; i++) {
        int n = n0 + po + 16 * i;
        if (n < N) {
            float px = p[(size_t)n * 3 + 0];
            float py = p[(size_t)n * 3 + 1];
            float pz = p[(size_t)n * 3 + 2];
            __half2 hh[4];
#pragma unroll
            for (int j = 0; j < 4; j++) {
                float2 a = upk2(acc[i][j]);
                int o = ob + 2 * j;
                float v0 = a.x + fmaf(px, wxs[o + 0], fmaf(py, wys[o + 0], pz * wzs[o + 0]));
                float v1 = a.y + fmaf(px, wxs[o + 1], fmaf(py, wys[o + 1], pz * wzs[o + 1]));
                hh[j] = __floats2half2_rn(v0, v1);
            }
            *(uint4*)((char*)g_H2 + (size_t)n * 128 + oo * 16) = *(const uint4*)hh;
        }
    }
}

// ---------------------------------------------------------------------------
// Stage 2: unchanged from R3 (warp-per-8-points, fp16 gather-max, paired-c
// matvec3).
// ---------------------------------------------------------------------------
__global__ __launch_bounds__(256, 4) void stage2_kernel(
    const float* __restrict__ p, const float* __restrict__ x,
    const int* __restrict__ idx, const float* __restrict__ conv_w,
    const float* __restrict__ g2, const float* __restrict__ b2,
    const float* __restrict__ m2, const float* __restrict__ v2,
    const float* __restrict__ w3,
    const float* __restrict__ g3, const float* __restrict__ b3,
    const float* __restrict__ m3, const float* __restrict__ v3,
    float* __restrict__ out, int N)
{
    __shared__ __align__(16) ulonglong2 w3r[32 * 32];   // 16 KB
    __shared__ __align__(16) ull fspk[64][64];          // 32 KB
    __shared__ float wxs[64], wys[64], wzs[64];
    __shared__ float s2s[64], t2s[64], s3s[64], t3s[64];

    const int tid = threadIdx.x;
    for (int e = tid; e < 1024; e += 256) {
        int c2 = e >> 5, l = e & 31;
        int c = 2 * c2, o = 2 * l;
        ulonglong2 v;
        v.x = pk2(w3[c * 64 + o], w3[c * 64 + o + 1]);
        v.y = pk2(w3[(c + 1) * 64 + o], w3[(c + 1) * 64 + o + 1]);
        w3r[e] = v;
    }
    if (tid < 64) {
        wxs[tid] = conv_w[tid * 67 + 0];
        wys[tid] = conv_w[tid * 67 + 1];
        wzs[tid] = conv_w[tid * 67 + 2];
        float s2 = g2[tid] * rsqrtf(v2[tid] + EPS);
        s2s[tid] = s2;
        t2s[tid] = b2[tid] - m2[tid] * s2;
        float s3 = g3[tid] * rsqrtf(v3[tid] + EPS);
        s3s[tid] = s3;
        t3s[tid] = b3[tid] - m3[tid] * s3;
    }
    __syncthreads();

    const int w = tid >> 5;
    const int t = tid & 31;
    const int n0 = blockIdx.x * 64 + w * 8;
    if (n0 >= N) return;

    const int o0 = 2 * t;
    const int pl0 = w * 8;

    const int* ib = idx + (size_t)n0 * 16;
    int i0 = ib[t], i1 = ib[32 + t], i2 = ib[64 + t], i3 = ib[96 + t];

    {
        const float sb20 = s2s[o0], sb21 = s2s[o0 + 1];
        const float tb20 = t2s[o0], tb21 = t2s[o0 + 1];
        const float wx0 = wxs[o0], wx1 = wxs[o0 + 1];
        const float wy0 = wys[o0], wy1 = wys[o0 + 1];
        const float wz0 = wzs[o0], wz1 = wzs[o0 + 1];
#pragma unroll
        for (int pt = 0; pt < 8; pt++) {
            const int n = n0 + pt;
            float px = p[(size_t)n * 3 + 0];
            float py = p[(size_t)n * 3 + 1];
            float pz = p[(size_t)n * 3 + 2];
            float c0 = fmaf(px, wx0, fmaf(py, wy0, pz * wz0));
            float c1 = fmaf(px, wx1, fmaf(py, wy1, pz * wz1));

            __half2 mv = __float2half2_rn(-CUDART_INF_F);
#pragma unroll
            for (int k = 0; k < 16; k++) {
                const int s = pt * 16 + k;
                int v = (s < 32) ? i0 : (s < 64) ? i1 : (s < 96) ? i2 : i3;
                int m = __shfl_sync(0xffffffffu, v, s & 31);
                mv = __hmax2(mv, g_H2[(size_t)m * 32 + t]);
            }
            float2 mf = __half22float2(mv);
            float f0 = fmaxf(fmaf(mf.x - c0, sb20, tb20), 0.f);
            float f1 = fmaxf(fmaf(mf.y - c1, sb21, tb21), 0.f);
            ulonglong2 st;
            st.x = pk2(f0, f0);
            st.y = pk2(f1, f1);
            *(ulonglong2*)&fspk[pl0 + pt][o0] = st;
        }
    }
    __syncwarp();

    ull a[8];
#pragma unroll
    for (int pt = 0; pt < 8; pt++) a[pt] = 0ull;

#pragma unroll
    for (int c2 = 0; c2 < 32; c2++) {
        ulonglong2 wp = w3r[c2 * 32 + t];
#pragma unroll
        for (int pt = 0; pt < 8; pt++) {
            ulonglong2 fv = *(const ulonglong2*)&fspk[pl0 + pt][2 * c2];
            FMA2(a[pt], fv.x, wp.x, a[pt]);
            FMA2(a[pt], fv.y, wp.y, a[pt]);
        }
    }

    const float sb30 = s3s[o0], sb31 = s3s[o0 + 1];
    const float tb30 = t3s[o0], tb31 = t3s[o0 + 1];
#pragma unroll
    for (int pt = 0; pt < 8; pt++) {
        const int n = n0 + pt;
        float2 av = upk2(a[pt]);
        float2 xv = *(const float2*)(x + (size_t)n * 64 + o0);
        float r0 = fmaxf(fmaf(av.x, sb30, tb30) + xv.x, 0.f);
        float r1 = fmaxf(fmaf(av.y, sb31, tb31) + xv.y, 0.f);
        *(float2*)(out + (size_t)n * 64 + o0) = make_float2(r0, r1);
    }
}

extern "C" void kernel_launch(void* const* d_in, const int* in_sizes, int n_in,
                              void* d_out, int out_size)
{
    const float* p      = (const float*)d_in[0];
    const float* x      = (const float*)d_in[1];
    const int*   idx    = (const int*)  d_in[2];
    const float* w1     = (const float*)d_in[3];
    const float* g1     = (const float*)d_in[4];
    const float* b1     = (const float*)d_in[5];
    const float* m1     = (const float*)d_in[6];
    const float* v1     = (const float*)d_in[7];
    const float* conv_w = (const float*)d_in[8];
    const float* g2     = (const float*)d_in[9];
    const float* b2     = (const float*)d_in[10];
    const float* m2     = (const float*)d_in[11];
    const float* v2     = (const float*)d_in[12];
    const float* w3     = (const float*)d_in[13];
    const float* g3     = (const float*)d_in[14];
    const float* b3     = (const float*)d_in[15];
    const float* m3     = (const float*)d_in[16];
    const float* v3     = (const float*)d_in[17];
    float* out = (float*)d_out;

    const int N = in_sizes[0] / 3;

    cudaFuncSetAttribute(stage1_kernel,
                         cudaFuncAttributeMaxDynamicSharedMemorySize,
                         S1_SMEM_BYTES);
    stage1_kernel<<<(N + 127) / 128, 128, S1_SMEM_BYTES>>>(
        p, x, w1, g1, b1, m1, v1, conv_w, N);
    stage2_kernel<<<(N + 63) / 64, 256>>>(p, x, idx, conv_w,
                                          g2, b2, m2, v2, w3, g3, b3, m3, v3,
                                          out, N);
}

// round 5
// speedup vs baseline: 3.6908x; 1.7727x over previous
#include <cuda_runtime.h>
#include <cuda_fp16.h>
#include <math_constants.h>

#define EPS 1e-5f
#define NMAX 100000
typedef unsigned int uint;

// Gather table: H2'[n][o] fp16, row = 64 halves = 128 B.
__device__ __half2 g_H2[(size_t)NMAX * 32];

// mma.sync m16n8k16, fp16 inputs, fp32 accum (HMMA.16816 on sm_103a)
__device__ __forceinline__ void mma16816(float* c,
                                         uint a0, uint a1, uint a2, uint a3,
                                         uint b0, uint b1)
{
    asm volatile(
        "mma.sync.aligned.m16n8k16.row.col.f32.f16.f16.f32 "
        "{%0,%1,%2,%3}, {%4,%5,%6,%7}, {%8,%9}, {%0,%1,%2,%3};"
        : "+f"(c[0]), "+f"(c[1]), "+f"(c[2]), "+f"(c[3])
        : "r"(a0), "r"(a1), "r"(a2), "r"(a3), "r"(b0), "r"(b1));
}

#define PITCH 72   // smem row pitch in halves (144 B): conflict-free frag loads

// ---------------------------------------------------------------------------
// Stage 1: block = 128 points, 256 threads (8 warps), warp = m16 tile.
// GEMM1 (x@w1) -> bn1+relu on fragments -> h back to smem fp16 -> GEMM2
// (h@w2^T) -> +p.Wxyz -> fp16 rows -> coalesced copy to g_H2.
// ---------------------------------------------------------------------------
__global__ __launch_bounds__(256, 3) void stage1_kernel(
    const float* __restrict__ p, const float* __restrict__ x,
    const float* __restrict__ w1,
    const float* __restrict__ g1, const float* __restrict__ b1,
    const float* __restrict__ m1, const float* __restrict__ v1,
    const float* __restrict__ conv_w, int N)
{
    __shared__ __align__(16) __half xh[128 * PITCH];   // x -> h -> H2 rows
    __shared__ __align__(16) __half w1T[64 * PITCH];   // [o][c] = w1[c][o]
    __shared__ __align__(16) __half w2T[64 * PITCH];   // [o][c] = conv_w[o][3+c]
    __shared__ float s1s[64], t1s[64], wxs[64], wys[64], wzs[64];

    const int tid = threadIdx.x;
    const int n0 = blockIdx.x * 128;

    // ---- loaders ----
    const float4* xg = (const float4*)x;
#pragma unroll
    for (int it = 0; it < 8; it++) {
        int e = tid + it * 256;           // 2048 float4
        int pt = e >> 4, c4 = e & 15;
        int n = n0 + pt;
        float4 v = make_float4(0.f, 0.f, 0.f, 0.f);
        if (n < N) v = xg[(size_t)n * 16 + c4];
        __half2* d = (__half2*)&xh[pt * PITCH + c4 * 4];
        d[0] = __floats2half2_rn(v.x, v.y);
        d[1] = __floats2half2_rn(v.z, v.w);
    }
#pragma unroll
    for (int it = 0; it < 16; it++) {
        int i = tid + it * 256;
        int c = i >> 6, o = i & 63;
        w1T[o * PITCH + c] = __float2half(w1[i]);
    }
#pragma unroll
    for (int it = 0; it < 17; it++) {
        int i = tid + it * 256;
        if (i < 64 * 67) {
            int o = i / 67, r = i - o * 67;
            float v = conv_w[i];
            if (r >= 3)      w2T[o * PITCH + (r - 3)] = __float2half(v);
            else if (r == 0) wxs[o] = v;
            else if (r == 1) wys[o] = v;
            else             wzs[o] = v;
        }
    }
    if (tid < 64) {
        float s = g1[tid] * rsqrtf(v1[tid] + EPS);
        s1s[tid] = s;
        t1s[tid] = b1[tid] - m1[tid] * s;
    }
    __syncthreads();

    const int w = tid >> 5, l = tid & 31;
    const int gr = l >> 2, q = l & 3;
    const int rA = w * 16 + gr;           // fragment row (and rA+8)

    float acc[8][4];
#pragma unroll
    for (int nt = 0; nt < 8; nt++)
#pragma unroll
        for (int j = 0; j < 4; j++) acc[nt][j] = 0.f;

    // ---- GEMM1: C = x @ w1 ----
#pragma unroll
    for (int kt = 0; kt < 4; kt++) {
        int k0 = kt * 16 + 2 * q;
        uint a0 = *(const uint*)&xh[rA * PITCH + k0];
        uint a1 = *(const uint*)&xh[(rA + 8) * PITCH + k0];
        uint a2 = *(const uint*)&xh[rA * PITCH + k0 + 8];
        uint a3 = *(const uint*)&xh[(rA + 8) * PITCH + k0 + 8];
#pragma unroll
        for (int nt = 0; nt < 8; nt++) {
            uint b0 = *(const uint*)&w1T[(nt * 8 + gr) * PITCH + k0];
            uint b1 = *(const uint*)&w1T[(nt * 8 + gr) * PITCH + k0 + 8];
            mma16816(acc[nt], a0, a1, a2, a3, b0, b1);
        }
    }

    // ---- bn1 + relu on fragments -> h (fp16) back into xh (own rows) ----
#pragma unroll
    for (int nt = 0; nt < 8; nt++) {
        int c = nt * 8 + 2 * q;
        float2 sv = *(const float2*)&s1s[c];
        float2 tv = *(const float2*)&t1s[c];
        float h00 = fmaxf(fmaf(acc[nt][0], sv.x, tv.x), 0.f);
        float h01 = fmaxf(fmaf(acc[nt][1], sv.y, tv.y), 0.f);
        float h10 = fmaxf(fmaf(acc[nt][2], sv.x, tv.x), 0.f);
        float h11 = fmaxf(fmaf(acc[nt][3], sv.y, tv.y), 0.f);
        *(__half2*)&xh[rA * PITCH + c]       = __floats2half2_rn(h00, h01);
        *(__half2*)&xh[(rA + 8) * PITCH + c] = __floats2half2_rn(h10, h11);
#pragma unroll
        for (int j = 0; j < 4; j++) acc[nt][j] = 0.f;
    }
    __syncwarp();

    // ---- GEMM2: C = h @ w2^T ----
#pragma unroll
    for (int kt = 0; kt < 4; kt++) {
        int k0 = kt * 16 + 2 * q;
        uint a0 = *(const uint*)&xh[rA * PITCH + k0];
        uint a1 = *(const uint*)&xh[(rA + 8) * PITCH + k0];
        uint a2 = *(const uint*)&xh[rA * PITCH + k0 + 8];
        uint a3 = *(const uint*)&xh[(rA + 8) * PITCH + k0 + 8];
#pragma unroll
        for (int nt = 0; nt < 8; nt++) {
            uint b0 = *(const uint*)&w2T[(nt * 8 + gr) * PITCH + k0];
            uint b1 = *(const uint*)&w2T[(nt * 8 + gr) * PITCH + k0 + 8];
            mma16816(acc[nt], a0, a1, a2, a3, b0, b1);
        }
    }
    __syncwarp();

    // ---- epilogue: + p.Wxyz, fp16 pack into xh rows ----
    const int nA = n0 + rA, nB = nA + 8;
    float pxA = 0.f, pyA = 0.f, pzA = 0.f, pxB = 0.f, pyB = 0.f, pzB = 0.f;
    if (nA < N) { pxA = p[(size_t)nA * 3]; pyA = p[(size_t)nA * 3 + 1]; pzA = p[(size_t)nA * 3 + 2]; }
    if (nB < N) { pxB = p[(size_t)nB * 3]; pyB = p[(size_t)nB * 3 + 1]; pzB = p[(size_t)nB * 3 + 2]; }
#pragma unroll
    for (int nt = 0; nt < 8; nt++) {
        int c = nt * 8 + 2 * q;
        float wx0 = wxs[c], wx1 = wxs[c + 1];
        float wy0 = wys[c], wy1 = wys[c + 1];
        float wz0 = wzs[c], wz1 = wzs[c + 1];
        float v00 = acc[nt][0] + fmaf(pxA, wx0, fmaf(pyA, wy0, pzA * wz0));
        float v01 = acc[nt][1] + fmaf(pxA, wx1, fmaf(pyA, wy1, pzA * wz1));
        float v10 = acc[nt][2] + fmaf(pxB, wx0, fmaf(pyB, wy0, pzB * wz0));
        float v11 = acc[nt][3] + fmaf(pxB, wx1, fmaf(pyB, wy1, pzB * wz1));
        *(__half2*)&xh[rA * PITCH + c]       = __floats2half2_rn(v00, v01);
        *(__half2*)&xh[(rA + 8) * PITCH + c] = __floats2half2_rn(v10, v11);
    }
    __syncthreads();

    // ---- coalesced copy: 128 rows x 128 B -> g_H2 ----
#pragma unroll
    for (int it = 0; it < 4; it++) {
        int e = tid + it * 256;           // 1024 uint4
        int row = e >> 3, seg = e & 7;
        int n = n0 + row;
        if (n < N)
            *(uint4*)((char*)g_H2 + (size_t)n * 128 + seg * 16) =
                *(const uint4*)&xh[row * PITCH + seg * 8];
    }
}

// ---------------------------------------------------------------------------
// Stage 2: block = 64 points, 256 threads (8 warps).
// Phase A (warp-per-8-points): fp16 gather-max, bn2+relu after max, F fp16
// to smem. Phase B: block-wide mma 64x64x64 (warp = m16 tile x 4 n-tiles).
// Epilogue: bn3 + residual + relu from fragments.
// ---------------------------------------------------------------------------
__global__ __launch_bounds__(256, 4) void stage2_kernel(
    const float* __restrict__ p, const float* __restrict__ x,
    const int* __restrict__ idx, const float* __restrict__ conv_w,
    const float* __restrict__ g2, const float* __restrict__ b2,
    const float* __restrict__ m2, const float* __restrict__ v2,
    const float* __restrict__ w3,
    const float* __restrict__ g3, const float* __restrict__ b3,
    const float* __restrict__ m3, const float* __restrict__ v3,
    float* __restrict__ out, int N)
{
    __shared__ __align__(16) __half Fsh[64 * PITCH];
    __shared__ __align__(16) __half w3T[64 * PITCH];   // [o][c] = w3[c][o]
    __shared__ float wxs[64], wys[64], wzs[64];
    __shared__ float s2s[64], t2s[64], s3s[64], t3s[64];

    const int tid = threadIdx.x;
#pragma unroll
    for (int it = 0; it < 16; it++) {
        int i = tid + it * 256;
        int c = i >> 6, o = i & 63;
        w3T[o * PITCH + c] = __float2half(w3[i]);
    }
#pragma unroll
    for (int it = 0; it < 9; it++) {      // zero Fsh (tail-block safety)
        int e = tid + it * 256;
        if (e < 64 * PITCH / 2) ((uint*)Fsh)[e] = 0u;
    }
    if (tid < 64) {
        wxs[tid] = conv_w[tid * 67 + 0];
        wys[tid] = conv_w[tid * 67 + 1];
        wzs[tid] = conv_w[tid * 67 + 2];
        float s2 = g2[tid] * rsqrtf(v2[tid] + EPS);
        s2s[tid] = s2;
        t2s[tid] = b2[tid] - m2[tid] * s2;
        float s3 = g3[tid] * rsqrtf(v3[tid] + EPS);
        s3s[tid] = s3;
        t3s[tid] = b3[tid] - m3[tid] * s3;
    }
    __syncthreads();

    const int w = tid >> 5;
    const int t = tid & 31;
    const int n0 = blockIdx.x * 64;
    const int n0w = n0 + w * 8;

    // ---- Phase A ----
    if (n0w < N) {                         // N % 8 == 0: warp all-valid
        const int o0 = 2 * t;
        const int* ib = idx + (size_t)n0w * 16;
        int i0 = ib[t], i1 = ib[32 + t], i2 = ib[64 + t], i3 = ib[96 + t];

        const float sb20 = s2s[o0], sb21 = s2s[o0 + 1];
        const float tb20 = t2s[o0], tb21 = t2s[o0 + 1];
        const float wx0 = wxs[o0], wx1 = wxs[o0 + 1];
        const float wy0 = wys[o0], wy1 = wys[o0 + 1];
        const float wz0 = wzs[o0], wz1 = wzs[o0 + 1];
#pragma unroll
        for (int pt = 0; pt < 8; pt++) {
            const int n = n0w + pt;
            float px = p[(size_t)n * 3 + 0];
            float py = p[(size_t)n * 3 + 1];
            float pz = p[(size_t)n * 3 + 2];
            float c0 = fmaf(px, wx0, fmaf(py, wy0, pz * wz0));
            float c1 = fmaf(px, wx1, fmaf(py, wy1, pz * wz1));

            __half2 mv = __float2half2_rn(-CUDART_INF_F);
#pragma unroll
            for (int k = 0; k < 16; k++) {
                const int s = pt * 16 + k;
                int v = (s < 32) ? i0 : (s < 64) ? i1 : (s < 96) ? i2 : i3;
                int m = __shfl_sync(0xffffffffu, v, s & 31);
                mv = __hmax2(mv, g_H2[(size_t)m * 32 + t]);
            }
            float2 mf = __half22float2(mv);
            float f0 = fmaxf(fmaf(mf.x - c0, sb20, tb20), 0.f);
            float f1 = fmaxf(fmaf(mf.y - c1, sb21, tb21), 0.f);
            *(__half2*)&Fsh[(w * 8 + pt) * PITCH + o0] = __floats2half2_rn(f0, f1);
        }
    }
    __syncthreads();

    // ---- Phase B: C = F @ w3 via mma; warp = m-tile (w&3), n-half (w>>2) ----
    const int gr = t >> 2, q = t & 3;
    const int mt = w & 3, nh = w >> 2;
    const int rA = mt * 16 + gr;

    float acc[4][4];
#pragma unroll
    for (int j = 0; j < 4; j++)
#pragma unroll
        for (int i = 0; i < 4; i++) acc[j][i] = 0.f;

#pragma unroll
    for (int kt = 0; kt < 4; kt++) {
        int k0 = kt * 16 + 2 * q;
        uint a0 = *(const uint*)&Fsh[rA * PITCH + k0];
        uint a1 = *(const uint*)&Fsh[(rA + 8) * PITCH + k0];
        uint a2 = *(const uint*)&Fsh[rA * PITCH + k0 + 8];
        uint a3 = *(const uint*)&Fsh[(rA + 8) * PITCH + k0 + 8];
#pragma unroll
        for (int j = 0; j < 4; j++) {
            int nr = (nh * 4 + j) * 8 + gr;
            uint b0 = *(const uint*)&w3T[nr * PITCH + k0];
            uint b1 = *(const uint*)&w3T[nr * PITCH + k0 + 8];
            mma16816(acc[j], a0, a1, a2, a3, b0, b1);
        }
    }

    // ---- epilogue: bn3 + residual + relu ----
    const int nA = n0 + rA, nB = nA + 8;
#pragma unroll
    for (int j = 0; j < 4; j++) {
        int c = (nh * 4 + j) * 8 + 2 * q;
        float2 sv = *(const float2*)&s3s[c];
        float2 tv = *(const float2*)&t3s[c];
        if (nA < N) {
            float2 xv = *(const float2*)&x[(size_t)nA * 64 + c];
            float r0 = fmaxf(fmaf(acc[j][0], sv.x, tv.x) + xv.x, 0.f);
            float r1 = fmaxf(fmaf(acc[j][1], sv.y, tv.y) + xv.y, 0.f);
            *(float2*)&out[(size_t)nA * 64 + c] = make_float2(r0, r1);
        }
        if (nB < N) {
            float2 xv = *(const float2*)&x[(size_t)nB * 64 + c];
            float r0 = fmaxf(fmaf(acc[j][2], sv.x, tv.x) + xv.x, 0.f);
            float r1 = fmaxf(fmaf(acc[j][3], sv.y, tv.y) + xv.y, 0.f);
            *(float2*)&out[(size_t)nB * 64 + c] = make_float2(r0, r1);
        }
    }
}

extern "C" void kernel_launch(void* const* d_in, const int* in_sizes, int n_in,
                              void* d_out, int out_size)
{
    const float* p      = (const float*)d_in[0];
    const float* x      = (const float*)d_in[1];
    const int*   idx    = (const int*)  d_in[2];
    const float* w1     = (const float*)d_in[3];
    const float* g1     = (const float*)d_in[4];
    const float* b1     = (const float*)d_in[5];
    const float* m1     = (const float*)d_in[6];
    const float* v1     = (const float*)d_in[7];
    const float* conv_w = (const float*)d_in[8];
    const float* g2     = (const float*)d_in[9];
    const float* b2     = (const float*)d_in[10];
    const float* m2     = (const float*)d_in[11];
    const float* v2     = (const float*)d_in[12];
    const float* w3     = (const float*)d_in[13];
    const float* g3     = (const float*)d_in[14];
    const float* b3     = (const float*)d_in[15];
    const float* m3     = (const float*)d_in[16];
    const float* v3     = (const float*)d_in[17];
    float* out = (float*)d_out;

    const int N = in_sizes[0] / 3;

    stage1_kernel<<<(N + 127) / 128, 256>>>(p, x, w1, g1, b1, m1, v1, conv_w, N);
    stage2_kernel<<<(N + 63) / 64, 256>>>(p, x, idx, conv_w,
                                          g2, b2, m2, v2, w3, g3, b3, m3, v3,
                                          out, N);
}

// round 6
// speedup vs baseline: 3.9720x; 1.0762x over previous
#include <cuda_runtime.h>
#include <cuda_fp16.h>
#include <math_constants.h>

#define EPS 1e-5f
#define NMAX 100000
typedef unsigned int uint;

// Gather table: H2'[n][o] fp16, row = 64 halves = 128 B.
__device__ __half2 g_H2[(size_t)NMAX * 32];

// mma.sync m16n8k16, fp16 inputs, fp32 accum (HMMA.16816 on sm_103a)
__device__ __forceinline__ void mma16816(float* c,
                                         uint a0, uint a1, uint a2, uint a3,
                                         uint b0, uint b1)
{
    asm volatile(
        "mma.sync.aligned.m16n8k16.row.col.f32.f16.f16.f32 "
        "{%0,%1,%2,%3}, {%4,%5,%6,%7}, {%8,%9}, {%0,%1,%2,%3};"
        : "+f"(c[0]), "+f"(c[1]), "+f"(c[2]), "+f"(c[3])
        : "r"(a0), "r"(a1), "r"(a2), "r"(a3), "r"(b0), "r"(b1));
}

#define PITCH 72   // smem row pitch in halves (144 B): conflict-free frag loads

// ---------------------------------------------------------------------------
// Stage 1: block = 128 points, 256 threads (8 warps), warp = m16 tile.
// GEMM1 (x@w1) -> bn1+relu on fragments -> h back to smem fp16 -> GEMM2
// (h@w2^T) -> +p.Wxyz -> fp16 rows -> coalesced copy to g_H2.  (R5 verbatim)
// ---------------------------------------------------------------------------
__global__ __launch_bounds__(256, 3) void stage1_kernel(
    const float* __restrict__ p, const float* __restrict__ x,
    const float* __restrict__ w1,
    const float* __restrict__ g1, const float* __restrict__ b1,
    const float* __restrict__ m1, const float* __restrict__ v1,
    const float* __restrict__ conv_w, int N)
{
    __shared__ __align__(16) __half xh[128 * PITCH];
    __shared__ __align__(16) __half w1T[64 * PITCH];
    __shared__ __align__(16) __half w2T[64 * PITCH];
    __shared__ float s1s[64], t1s[64], wxs[64], wys[64], wzs[64];

    const int tid = threadIdx.x;
    const int n0 = blockIdx.x * 128;

    const float4* xg = (const float4*)x;
#pragma unroll
    for (int it = 0; it < 8; it++) {
        int e = tid + it * 256;
        int pt = e >> 4, c4 = e & 15;
        int n = n0 + pt;
        float4 v = make_float4(0.f, 0.f, 0.f, 0.f);
        if (n < N) v = xg[(size_t)n * 16 + c4];
        __half2* d = (__half2*)&xh[pt * PITCH + c4 * 4];
        d[0] = __floats2half2_rn(v.x, v.y);
        d[1] = __floats2half2_rn(v.z, v.w);
    }
#pragma unroll
    for (int it = 0; it < 16; it++) {
        int i = tid + it * 256;
        int c = i >> 6, o = i & 63;
        w1T[o * PITCH + c] = __float2half(w1[i]);
    }
#pragma unroll
    for (int it = 0; it < 17; it++) {
        int i = tid + it * 256;
        if (i < 64 * 67) {
            int o = i / 67, r = i - o * 67;
            float v = conv_w[i];
            if (r >= 3)      w2T[o * PITCH + (r - 3)] = __float2half(v);
            else if (r == 0) wxs[o] = v;
            else if (r == 1) wys[o] = v;
            else             wzs[o] = v;
        }
    }
    if (tid < 64) {
        float s = g1[tid] * rsqrtf(v1[tid] + EPS);
        s1s[tid] = s;
        t1s[tid] = b1[tid] - m1[tid] * s;
    }
    __syncthreads();

    const int w = tid >> 5, l = tid & 31;
    const int gr = l >> 2, q = l & 3;
    const int rA = w * 16 + gr;

    float acc[8][4];
#pragma unroll
    for (int nt = 0; nt < 8; nt++)
#pragma unroll
        for (int j = 0; j < 4; j++) acc[nt][j] = 0.f;

#pragma unroll
    for (int kt = 0; kt < 4; kt++) {
        int k0 = kt * 16 + 2 * q;
        uint a0 = *(const uint*)&xh[rA * PITCH + k0];
        uint a1 = *(const uint*)&xh[(rA + 8) * PITCH + k0];
        uint a2 = *(const uint*)&xh[rA * PITCH + k0 + 8];
        uint a3 = *(const uint*)&xh[(rA + 8) * PITCH + k0 + 8];
#pragma unroll
        for (int nt = 0; nt < 8; nt++) {
            uint b0 = *(const uint*)&w1T[(nt * 8 + gr) * PITCH + k0];
            uint b1 = *(const uint*)&w1T[(nt * 8 + gr) * PITCH + k0 + 8];
            mma16816(acc[nt], a0, a1, a2, a3, b0, b1);
        }
    }

#pragma unroll
    for (int nt = 0; nt < 8; nt++) {
        int c = nt * 8 + 2 * q;
        float2 sv = *(const float2*)&s1s[c];
        float2 tv = *(const float2*)&t1s[c];
        float h00 = fmaxf(fmaf(acc[nt][0], sv.x, tv.x), 0.f);
        float h01 = fmaxf(fmaf(acc[nt][1], sv.y, tv.y), 0.f);
        float h10 = fmaxf(fmaf(acc[nt][2], sv.x, tv.x), 0.f);
        float h11 = fmaxf(fmaf(acc[nt][3], sv.y, tv.y), 0.f);
        *(__half2*)&xh[rA * PITCH + c]       = __floats2half2_rn(h00, h01);
        *(__half2*)&xh[(rA + 8) * PITCH + c] = __floats2half2_rn(h10, h11);
#pragma unroll
        for (int j = 0; j < 4; j++) acc[nt][j] = 0.f;
    }
    __syncwarp();

#pragma unroll
    for (int kt = 0; kt < 4; kt++) {
        int k0 = kt * 16 + 2 * q;
        uint a0 = *(const uint*)&xh[rA * PITCH + k0];
        uint a1 = *(const uint*)&xh[(rA + 8) * PITCH + k0];
        uint a2 = *(const uint*)&xh[rA * PITCH + k0 + 8];
        uint a3 = *(const uint*)&xh[(rA + 8) * PITCH + k0 + 8];
#pragma unroll
        for (int nt = 0; nt < 8; nt++) {
            uint b0 = *(const uint*)&w2T[(nt * 8 + gr) * PITCH + k0];
            uint b1 = *(const uint*)&w2T[(nt * 8 + gr) * PITCH + k0 + 8];
            mma16816(acc[nt], a0, a1, a2, a3, b0, b1);
        }
    }
    __syncwarp();

    const int nA = n0 + rA, nB = nA + 8;
    float pxA = 0.f, pyA = 0.f, pzA = 0.f, pxB = 0.f, pyB = 0.f, pzB = 0.f;
    if (nA < N) { pxA = p[(size_t)nA * 3]; pyA = p[(size_t)nA * 3 + 1]; pzA = p[(size_t)nA * 3 + 2]; }
    if (nB < N) { pxB = p[(size_t)nB * 3]; pyB = p[(size_t)nB * 3 + 1]; pzB = p[(size_t)nB * 3 + 2]; }
#pragma unroll
    for (int nt = 0; nt < 8; nt++) {
        int c = nt * 8 + 2 * q;
        float wx0 = wxs[c], wx1 = wxs[c + 1];
        float wy0 = wys[c], wy1 = wys[c + 1];
        float wz0 = wzs[c], wz1 = wzs[c + 1];
        float v00 = acc[nt][0] + fmaf(pxA, wx0, fmaf(pyA, wy0, pzA * wz0));
        float v01 = acc[nt][1] + fmaf(pxA, wx1, fmaf(pyA, wy1, pzA * wz1));
        float v10 = acc[nt][2] + fmaf(pxB, wx0, fmaf(pyB, wy0, pzB * wz0));
        float v11 = acc[nt][3] + fmaf(pxB, wx1, fmaf(pyB, wy1, pzB * wz1));
        *(__half2*)&xh[rA * PITCH + c]       = __floats2half2_rn(v00, v01);
        *(__half2*)&xh[(rA + 8) * PITCH + c] = __floats2half2_rn(v10, v11);
    }
    __syncthreads();

#pragma unroll
    for (int it = 0; it < 4; it++) {
        int e = tid + it * 256;
        int row = e >> 3, seg = e & 7;
        int n = n0 + row;
        if (n < N)
            *(uint4*)((char*)g_H2 + (size_t)n * 128 + seg * 16) =
                *(const uint4*)&xh[row * PITCH + seg * 8];
    }
}

// ---------------------------------------------------------------------------
// Stage 2: block = 64 points, 256 threads (8 warps), 5 blocks/SM.
// Indices staged in smem (no shuffles); gathers use 32-bit shifted addressing.
// Phase B: block-wide mma 64x64x64. Epilogue: bn3 + residual + relu.
// ---------------------------------------------------------------------------
__global__ __launch_bounds__(256, 5) void stage2_kernel(
    const float* __restrict__ p, const float* __restrict__ x,
    const int* __restrict__ idx, const float* __restrict__ conv_w,
    const float* __restrict__ g2, const float* __restrict__ b2,
    const float* __restrict__ m2, const float* __restrict__ v2,
    const float* __restrict__ w3,
    const float* __restrict__ g3, const float* __restrict__ b3,
    const float* __restrict__ m3, const float* __restrict__ v3,
    float* __restrict__ out, int N)
{
    __shared__ __align__(16) __half Fsh[64 * PITCH];
    __shared__ __align__(16) __half w3T[64 * PITCH];   // [o][c] = w3[c][o]
    __shared__ __align__(16) int idxs[1024];           // 64 pts x 16 neighbors
    __shared__ float wxs[64], wys[64], wzs[64];
    __shared__ float s2s[64], t2s[64], s3s[64], t3s[64];

    const int tid = threadIdx.x;
    const int n0 = blockIdx.x * 64;

#pragma unroll
    for (int it = 0; it < 16; it++) {
        int i = tid + it * 256;
        int c = i >> 6, o = i & 63;
        w3T[o * PITCH + c] = __float2half(w3[i]);
    }
    // zero Fsh (tail-block rows must be 0 for the mma)
#pragma unroll
    for (int it = 0; it < 3; it++) {
        int e = tid + it * 256;
        if (e < 64 * PITCH / 8) ((uint4*)Fsh)[e] = make_uint4(0u, 0u, 0u, 0u);
    }
    // stage this block's neighbor indices (coalesced int4)
    if (tid < (N - n0) * 4)
        *(int4*)&idxs[tid * 4] = ((const int4*)(idx + (size_t)n0 * 16))[tid];
    if (tid < 64) {
        wxs[tid] = conv_w[tid * 67 + 0];
        wys[tid] = conv_w[tid * 67 + 1];
        wzs[tid] = conv_w[tid * 67 + 2];
        float s2 = g2[tid] * rsqrtf(v2[tid] + EPS);
        s2s[tid] = s2;
        t2s[tid] = b2[tid] - m2[tid] * s2;
        float s3 = g3[tid] * rsqrtf(v3[tid] + EPS);
        s3s[tid] = s3;
        t3s[tid] = b3[tid] - m3[tid] * s3;
    }
    __syncthreads();

    const int w = tid >> 5;
    const int t = tid & 31;
    const int n0w = n0 + w * 8;

    // ---- Phase A: gather-max + bn2 + relu, F -> smem fp16 ----
    if (n0w < N) {                         // N % 8 == 0: warp all-valid
        const int o0 = 2 * t;
        const int* wib = &idxs[w * 128];
        const char* basep = (const char*)g_H2 + 4 * t;

        const float sb20 = s2s[o0], sb21 = s2s[o0 + 1];
        const float tb20 = t2s[o0], tb21 = t2s[o0 + 1];
        const float wx0 = wxs[o0], wx1 = wxs[o0 + 1];
        const float wy0 = wys[o0], wy1 = wys[o0 + 1];
        const float wz0 = wzs[o0], wz1 = wzs[o0 + 1];
#pragma unroll
        for (int pt = 0; pt < 8; pt++) {
            const int n = n0w + pt;
            float px = p[(size_t)n * 3 + 0];
            float py = p[(size_t)n * 3 + 1];
            float pz = p[(size_t)n * 3 + 2];
            float c0 = fmaf(px, wx0, fmaf(py, wy0, pz * wz0));
            float c1 = fmaf(px, wx1, fmaf(py, wy1, pz * wz1));

            __half2 mv = __float2half2_rn(-CUDART_INF_F);
#pragma unroll
            for (int k = 0; k < 16; k++) {
                uint m = (uint)wib[pt * 16 + k];
                mv = __hmax2(mv, *(const __half2*)(basep + ((size_t)(m << 7))));
            }
            float2 mf = __half22float2(mv);
            float f0 = fmaxf(fmaf(mf.x - c0, sb20, tb20), 0.f);
            float f1 = fmaxf(fmaf(mf.y - c1, sb21, tb21), 0.f);
            *(__half2*)&Fsh[(w * 8 + pt) * PITCH + o0] = __floats2half2_rn(f0, f1);
        }
    }
    __syncthreads();

    // ---- Phase B: C = F @ w3 via mma; warp = m-tile (w&3), n-half (w>>2) ----
    const int gr = t >> 2, q = t & 3;
    const int mt = w & 3, nh = w >> 2;
    const int rA = mt * 16 + gr;

    float acc[4][4];
#pragma unroll
    for (int j = 0; j < 4; j++)
#pragma unroll
        for (int i = 0; i < 4; i++) acc[j][i] = 0.f;

#pragma unroll
    for (int kt = 0; kt < 4; kt++) {
        int k0 = kt * 16 + 2 * q;
        uint a0 = *(const uint*)&Fsh[rA * PITCH + k0];
        uint a1 = *(const uint*)&Fsh[(rA + 8) * PITCH + k0];
        uint a2 = *(const uint*)&Fsh[rA * PITCH + k0 + 8];
        uint a3 = *(const uint*)&Fsh[(rA + 8) * PITCH + k0 + 8];
#pragma unroll
        for (int j = 0; j < 4; j++) {
            int nr = (nh * 4 + j) * 8 + gr;
            uint b0 = *(const uint*)&w3T[nr * PITCH + k0];
            uint b1 = *(const uint*)&w3T[nr * PITCH + k0 + 8];
            mma16816(acc[j], a0, a1, a2, a3, b0, b1);
        }
    }

    // ---- epilogue: bn3 + residual + relu ----
    const int nA = n0 + rA, nB = nA + 8;
#pragma unroll
    for (int j = 0; j < 4; j++) {
        int c = (nh * 4 + j) * 8 + 2 * q;
        float2 sv = *(const float2*)&s3s[c];
        float2 tv = *(const float2*)&t3s[c];
        if (nA < N) {
            float2 xv = *(const float2*)&x[(size_t)nA * 64 + c];
            float r0 = fmaxf(fmaf(acc[j][0], sv.x, tv.x) + xv.x, 0.f);
            float r1 = fmaxf(fmaf(acc[j][1], sv.y, tv.y) + xv.y, 0.f);
            *(float2*)&out[(size_t)nA * 64 + c] = make_float2(r0, r1);
        }
        if (nB < N) {
            float2 xv = *(const float2*)&x[(size_t)nB * 64 + c];
            float r0 = fmaxf(fmaf(acc[j][2], sv.x, tv.x) + xv.x, 0.f);
            float r1 = fmaxf(fmaf(acc[j][3], sv.y, tv.y) + xv.y, 0.f);
            *(float2*)&out[(size_t)nB * 64 + c] = make_float2(r0, r1);
        }
    }
}

extern "C" void kernel_launch(void* const* d_in, const int* in_sizes, int n_in,
                              void* d_out, int out_size)
{
    const float* p      = (const float*)d_in[0];
    const float* x      = (const float*)d_in[1];
    const int*   idx    = (const int*)  d_in[2];
    const float* w1     = (const float*)d_in[3];
    const float* g1     = (const float*)d_in[4];
    const float* b1     = (const float*)d_in[5];
    const float* m1     = (const float*)d_in[6];
    const float* v1     = (const float*)d_in[7];
    const float* conv_w = (const float*)d_in[8];
    const float* g2     = (const float*)d_in[9];
    const float* b2     = (const float*)d_in[10];
    const float* m2     = (const float*)d_in[11];
    const float* v2     = (const float*)d_in[12];
    const float* w3     = (const float*)d_in[13];
    const float* g3     = (const float*)d_in[14];
    const float* b3     = (const float*)d_in[15];
    const float* m3     = (const float*)d_in[16];
    const float* v3     = (const float*)d_in[17];
    float* out = (float*)d_out;

    const int N = in_sizes[0] / 3;

    stage1_kernel<<<(N + 127) / 128, 256>>>(p, x, w1, g1, b1, m1, v1, conv_w, N);
    stage2_kernel<<<(N + 63) / 64, 256>>>(p, x, idx, conv_w,
                                          g2, b2, m2, v2, w3, g3, b3, m3, v3,
                                          out, N);
}

// round 7
// speedup vs baseline: 3.9958x; 1.0060x over previous
#include <cuda_runtime.h>
#include <cuda_fp16.h>
#include <math_constants.h>

#define EPS 1e-5f
#define NMAX 100000
typedef unsigned int uint;

// Gather table: H2'[n][o] fp16, row = 64 halves = 128 B.
__device__ __half2 g_H2[(size_t)NMAX * 32];

// mma.sync m16n8k16, fp16 inputs, fp32 accum (HMMA.16816 on sm_103a)
__device__ __forceinline__ void mma16816(float* c,
                                         uint a0, uint a1, uint a2, uint a3,
                                         uint b0, uint b1)
{
    asm volatile(
        "mma.sync.aligned.m16n8k16.row.col.f32.f16.f16.f32 "
        "{%0,%1,%2,%3}, {%4,%5,%6,%7}, {%8,%9}, {%0,%1,%2,%3};"
        : "+f"(c[0]), "+f"(c[1]), "+f"(c[2]), "+f"(c[3])
        : "r"(a0), "r"(a1), "r"(a2), "r"(a3), "r"(b0), "r"(b1));
}

#define PITCH 72   // smem row pitch in halves (144 B): conflict-free frag loads

// ---------------------------------------------------------------------------
// Stage 1: block = 128 points, 256 threads (8 warps), warp = m16 tile.
// (R5/R6 verbatim — proven at ~16us.)
// ---------------------------------------------------------------------------
__global__ __launch_bounds__(256, 3) void stage1_kernel(
    const float* __restrict__ p, const float* __restrict__ x,
    const float* __restrict__ w1,
    const float* __restrict__ g1, const float* __restrict__ b1,
    const float* __restrict__ m1, const float* __restrict__ v1,
    const float* __restrict__ conv_w, int N)
{
    __shared__ __align__(16) __half xh[128 * PITCH];
    __shared__ __align__(16) __half w1T[64 * PITCH];
    __shared__ __align__(16) __half w2T[64 * PITCH];
    __shared__ float s1s[64], t1s[64], wxs[64], wys[64], wzs[64];

    const int tid = threadIdx.x;
    const int n0 = blockIdx.x * 128;

    const float4* xg = (const float4*)x;
#pragma unroll
    for (int it = 0; it < 8; it++) {
        int e = tid + it * 256;
        int pt = e >> 4, c4 = e & 15;
        int n = n0 + pt;
        float4 v = make_float4(0.f, 0.f, 0.f, 0.f);
        if (n < N) v = xg[(size_t)n * 16 + c4];
        __half2* d = (__half2*)&xh[pt * PITCH + c4 * 4];
        d[0] = __floats2half2_rn(v.x, v.y);
        d[1] = __floats2half2_rn(v.z, v.w);
    }
#pragma unroll
    for (int it = 0; it < 16; it++) {
        int i = tid + it * 256;
        int c = i >> 6, o = i & 63;
        w1T[o * PITCH + c] = __float2half(w1[i]);
    }
#pragma unroll
    for (int it = 0; it < 17; it++) {
        int i = tid + it * 256;
        if (i < 64 * 67) {
            int o = i / 67, r = i - o * 67;
            float v = conv_w[i];
            if (r >= 3)      w2T[o * PITCH + (r - 3)] = __float2half(v);
            else if (r == 0) wxs[o] = v;
            else if (r == 1) wys[o] = v;
            else             wzs[o] = v;
        }
    }
    if (tid < 64) {
        float s = g1[tid] * rsqrtf(v1[tid] + EPS);
        s1s[tid] = s;
        t1s[tid] = b1[tid] - m1[tid] * s;
    }
    __syncthreads();

    const int w = tid >> 5, l = tid & 31;
    const int gr = l >> 2, q = l & 3;
    const int rA = w * 16 + gr;

    float acc[8][4];
#pragma unroll
    for (int nt = 0; nt < 8; nt++)
#pragma unroll
        for (int j = 0; j < 4; j++) acc[nt][j] = 0.f;

#pragma unroll
    for (int kt = 0; kt < 4; kt++) {
        int k0 = kt * 16 + 2 * q;
        uint a0 = *(const uint*)&xh[rA * PITCH + k0];
        uint a1 = *(const uint*)&xh[(rA + 8) * PITCH + k0];
        uint a2 = *(const uint*)&xh[rA * PITCH + k0 + 8];
        uint a3 = *(const uint*)&xh[(rA + 8) * PITCH + k0 + 8];
#pragma unroll
        for (int nt = 0; nt < 8; nt++) {
            uint b0 = *(const uint*)&w1T[(nt * 8 + gr) * PITCH + k0];
            uint b1 = *(const uint*)&w1T[(nt * 8 + gr) * PITCH + k0 + 8];
            mma16816(acc[nt], a0, a1, a2, a3, b0, b1);
        }
    }

#pragma unroll
    for (int nt = 0; nt < 8; nt++) {
        int c = nt * 8 + 2 * q;
        float2 sv = *(const float2*)&s1s[c];
        float2 tv = *(const float2*)&t1s[c];
        float h00 = fmaxf(fmaf(acc[nt][0], sv.x, tv.x), 0.f);
        float h01 = fmaxf(fmaf(acc[nt][1], sv.y, tv.y), 0.f);
        float h10 = fmaxf(fmaf(acc[nt][2], sv.x, tv.x), 0.f);
        float h11 = fmaxf(fmaf(acc[nt][3], sv.y, tv.y), 0.f);
        *(__half2*)&xh[rA * PITCH + c]       = __floats2half2_rn(h00, h01);
        *(__half2*)&xh[(rA + 8) * PITCH + c] = __floats2half2_rn(h10, h11);
#pragma unroll
        for (int j = 0; j < 4; j++) acc[nt][j] = 0.f;
    }
    __syncwarp();

#pragma unroll
    for (int kt = 0; kt < 4; kt++) {
        int k0 = kt * 16 + 2 * q;
        uint a0 = *(const uint*)&xh[rA * PITCH + k0];
        uint a1 = *(const uint*)&xh[(rA + 8) * PITCH + k0];
        uint a2 = *(const uint*)&xh[rA * PITCH + k0 + 8];
        uint a3 = *(const uint*)&xh[(rA + 8) * PITCH + k0 + 8];
#pragma unroll
        for (int nt = 0; nt < 8; nt++) {
            uint b0 = *(const uint*)&w2T[(nt * 8 + gr) * PITCH + k0];
            uint b1 = *(const uint*)&w2T[(nt * 8 + gr) * PITCH + k0 + 8];
            mma16816(acc[nt], a0, a1, a2, a3, b0, b1);
        }
    }
    __syncwarp();

    const int nA = n0 + rA, nB = nA + 8;
    float pxA = 0.f, pyA = 0.f, pzA = 0.f, pxB = 0.f, pyB = 0.f, pzB = 0.f;
    if (nA < N) { pxA = p[(size_t)nA * 3]; pyA = p[(size_t)nA * 3 + 1]; pzA = p[(size_t)nA * 3 + 2]; }
    if (nB < N) { pxB = p[(size_t)nB * 3]; pyB = p[(size_t)nB * 3 + 1]; pzB = p[(size_t)nB * 3 + 2]; }
#pragma unroll
    for (int nt = 0; nt < 8; nt++) {
        int c = nt * 8 + 2 * q;
        float wx0 = wxs[c], wx1 = wxs[c + 1];
        float wy0 = wys[c], wy1 = wys[c + 1];
        float wz0 = wzs[c], wz1 = wzs[c + 1];
        float v00 = acc[nt][0] + fmaf(pxA, wx0, fmaf(pyA, wy0, pzA * wz0));
        float v01 = acc[nt][1] + fmaf(pxA, wx1, fmaf(pyA, wy1, pzA * wz1));
        float v10 = acc[nt][2] + fmaf(pxB, wx0, fmaf(pyB, wy0, pzB * wz0));
        float v11 = acc[nt][3] + fmaf(pxB, wx1, fmaf(pyB, wy1, pzB * wz1));
        *(__half2*)&xh[rA * PITCH + c]       = __floats2half2_rn(v00, v01);
        *(__half2*)&xh[(rA + 8) * PITCH + c] = __floats2half2_rn(v10, v11);
    }
    __syncthreads();

#pragma unroll
    for (int it = 0; it < 4; it++) {
        int e = tid + it * 256;
        int row = e >> 3, seg = e & 7;
        int n = n0 + row;
        if (n < N)
            *(uint4*)((char*)g_H2 + (size_t)n * 128 + seg * 16) =
                *(const uint4*)&xh[row * PITCH + seg * 8];
    }
}

// ---------------------------------------------------------------------------
// Stage 2: block = 64 points, 256 threads (8 warps), 5 blocks/SM.
// Phase A: int4 broadcast index loads, 16 batched gathers into regs, hmax
// tree reduction, p staged in smem. Phase B: block-wide mma 64x64x64.
// ---------------------------------------------------------------------------
__global__ __launch_bounds__(256, 5) void stage2_kernel(
    const float* __restrict__ p, const float* __restrict__ x,
    const int* __restrict__ idx, const float* __restrict__ conv_w,
    const float* __restrict__ g2, const float* __restrict__ b2,
    const float* __restrict__ m2, const float* __restrict__ v2,
    const float* __restrict__ w3,
    const float* __restrict__ g3, const float* __restrict__ b3,
    const float* __restrict__ m3, const float* __restrict__ v3,
    float* __restrict__ out, int N)
{
    __shared__ __align__(16) __half Fsh[64 * PITCH];
    __shared__ __align__(16) __half w3T[64 * PITCH];   // [o][c] = w3[c][o]
    __shared__ __align__(16) int idxs[1024];           // 64 pts x 16 neighbors
    __shared__ float ps[64 * 3];                        // p rows for this block
    __shared__ float wxs[64], wys[64], wzs[64];
    __shared__ float s2s[64], t2s[64], s3s[64], t3s[64];

    const int tid = threadIdx.x;
    const int n0 = blockIdx.x * 64;
    const int nblk = (N - n0 < 64) ? (N - n0) : 64;

#pragma unroll
    for (int it = 0; it < 16; it++) {
        int i = tid + it * 256;
        int c = i >> 6, o = i & 63;
        w3T[o * PITCH + c] = __float2half(w3[i]);
    }
    // zero Fsh (tail-block rows must be 0 for the mma)
#pragma unroll
    for (int it = 0; it < 3; it++) {
        int e = tid + it * 256;
        if (e < 64 * PITCH / 8) ((uint4*)Fsh)[e] = make_uint4(0u, 0u, 0u, 0u);
    }
    // stage this block's neighbor indices (coalesced int4) and p rows
    if (tid < nblk * 4)
        *(int4*)&idxs[tid * 4] = ((const int4*)(idx + (size_t)n0 * 16))[tid];
    if (tid < nblk * 3)
        ps[tid] = p[(size_t)n0 * 3 + tid];
    if (tid < 64) {
        wxs[tid] = conv_w[tid * 67 + 0];
        wys[tid] = conv_w[tid * 67 + 1];
        wzs[tid] = conv_w[tid * 67 + 2];
        float s2 = g2[tid] * rsqrtf(v2[tid] + EPS);
        s2s[tid] = s2;
        t2s[tid] = b2[tid] - m2[tid] * s2;
        float s3 = g3[tid] * rsqrtf(v3[tid] + EPS);
        s3s[tid] = s3;
        t3s[tid] = b3[tid] - m3[tid] * s3;
    }
    __syncthreads();

    const int w = tid >> 5;
    const int t = tid & 31;
    const int n0w = n0 + w * 8;

    // ---- Phase A: gather-max (batched loads + tree hmax) + bn2 + relu ----
    if (n0w < N) {                         // N % 8 == 0: warp all-valid
        const int o0 = 2 * t;
        const int4* wib4 = (const int4*)&idxs[w * 128];
        const char* basep = (const char*)g_H2 + 4 * t;

        const float sb20 = s2s[o0], sb21 = s2s[o0 + 1];
        const float tb20 = t2s[o0], tb21 = t2s[o0 + 1];
        const float wx0 = wxs[o0], wx1 = wxs[o0 + 1];
        const float wy0 = wys[o0], wy1 = wys[o0 + 1];
        const float wz0 = wzs[o0], wz1 = wzs[o0 + 1];
#pragma unroll
        for (int pt = 0; pt < 8; pt++) {
            // 16 neighbor indices via 4 broadcast LDS.128
            int4 ia = wib4[pt * 4 + 0];
            int4 ib = wib4[pt * 4 + 1];
            int4 ic = wib4[pt * 4 + 2];
            int4 id = wib4[pt * 4 + 3];

            // batch all 16 gathers into registers (MLP=16)
            __half2 v0  = *(const __half2*)(basep + ((size_t)((uint)ia.x << 7)));
            __half2 v1  = *(const __half2*)(basep + ((size_t)((uint)ia.y << 7)));
            __half2 v2_ = *(const __half2*)(basep + ((size_t)((uint)ia.z << 7)));
            __half2 v3_ = *(const __half2*)(basep + ((size_t)((uint)ia.w << 7)));
            __half2 v4  = *(const __half2*)(basep + ((size_t)((uint)ib.x << 7)));
            __half2 v5  = *(const __half2*)(basep + ((size_t)((uint)ib.y << 7)));
            __half2 v6  = *(const __half2*)(basep + ((size_t)((uint)ib.z << 7)));
            __half2 v7  = *(const __half2*)(basep + ((size_t)((uint)ib.w << 7)));
            __half2 v8  = *(const __half2*)(basep + ((size_t)((uint)ic.x << 7)));
            __half2 v9  = *(const __half2*)(basep + ((size_t)((uint)ic.y << 7)));
            __half2 v10 = *(const __half2*)(basep + ((size_t)((uint)ic.z << 7)));
            __half2 v11 = *(const __half2*)(basep + ((size_t)((uint)ic.w << 7)));
            __half2 v12 = *(const __half2*)(basep + ((size_t)((uint)id.x << 7)));
            __half2 v13 = *(const __half2*)(basep + ((size_t)((uint)id.y << 7)));
            __half2 v14 = *(const __half2*)(basep + ((size_t)((uint)id.z << 7)));
            __half2 v15 = *(const __half2*)(basep + ((size_t)((uint)id.w << 7)));

            // tree reduction
            v0  = __hmax2(v0, v1);   v2_ = __hmax2(v2_, v3_);
            v4  = __hmax2(v4, v5);   v6  = __hmax2(v6, v7);
            v8  = __hmax2(v8, v9);   v10 = __hmax2(v10, v11);
            v12 = __hmax2(v12, v13); v14 = __hmax2(v14, v15);
            v0  = __hmax2(v0, v2_);  v4  = __hmax2(v4, v6);
            v8  = __hmax2(v8, v10);  v12 = __hmax2(v12, v14);
            v0  = __hmax2(v0, v4);   v8  = __hmax2(v8, v12);
            v0  = __hmax2(v0, v8);

            // center offset from staged p
            const float* pr = &ps[(w * 8 + pt) * 3];
            float px = pr[0], py = pr[1], pz = pr[2];
            float c0 = fmaf(px, wx0, fmaf(py, wy0, pz * wz0));
            float c1 = fmaf(px, wx1, fmaf(py, wy1, pz * wz1));

            float2 mf = __half22float2(v0);
            float f0 = fmaxf(fmaf(mf.x - c0, sb20, tb20), 0.f);
            float f1 = fmaxf(fmaf(mf.y - c1, sb21, tb21), 0.f);
            *(__half2*)&Fsh[(w * 8 + pt) * PITCH + o0] = __floats2half2_rn(f0, f1);
        }
    }
    __syncthreads();

    // ---- Phase B: C = F @ w3 via mma; warp = m-tile (w&3), n-half (w>>2) ----
    const int gr = t >> 2, q = t & 3;
    const int mt = w & 3, nh = w >> 2;
    const int rA = mt * 16 + gr;

    float acc[4][4];
#pragma unroll
    for (int j = 0; j < 4; j++)
#pragma unroll
        for (int i = 0; i < 4; i++) acc[j][i] = 0.f;

#pragma unroll
    for (int kt = 0; kt < 4; kt++) {
        int k0 = kt * 16 + 2 * q;
        uint a0 = *(const uint*)&Fsh[rA * PITCH + k0];
        uint a1 = *(const uint*)&Fsh[(rA + 8) * PITCH + k0];
        uint a2 = *(const uint*)&Fsh[rA * PITCH + k0 + 8];
        uint a3 = *(const uint*)&Fsh[(rA + 8) * PITCH + k0 + 8];
#pragma unroll
        for (int j = 0; j < 4; j++) {
            int nr = (nh * 4 + j) * 8 + gr;
            uint b0 = *(const uint*)&w3T[nr * PITCH + k0];
            uint b1 = *(const uint*)&w3T[nr * PITCH + k0 + 8];
            mma16816(acc[j], a0, a1, a2, a3, b0, b1);
        }
    }

    // ---- epilogue: bn3 + residual + relu ----
    const int nA = n0 + rA, nB = nA + 8;
#pragma unroll
    for (int j = 0; j < 4; j++) {
        int c = (nh * 4 + j) * 8 + 2 * q;
        float2 sv = *(const float2*)&s3s[c];
        float2 tv = *(const float2*)&t3s[c];
        if (nA < N) {
            float2 xv = *(const float2*)&x[(size_t)nA * 64 + c];
            float r0 = fmaxf(fmaf(acc[j][0], sv.x, tv.x) + xv.x, 0.f);
            float r1 = fmaxf(fmaf(acc[j][1], sv.y, tv.y) + xv.y, 0.f);
            *(float2*)&out[(size_t)nA * 64 + c] = make_float2(r0, r1);
        }
        if (nB < N) {
            float2 xv = *(const float2*)&x[(size_t)nB * 64 + c];
            float r0 = fmaxf(fmaf(acc[j][2], sv.x, tv.x) + xv.x, 0.f);
            float r1 = fmaxf(fmaf(acc[j][3], sv.y, tv.y) + xv.y, 0.f);
            *(float2*)&out[(size_t)nB * 64 + c] = make_float2(r0, r1);
        }
    }
}

extern "C" void kernel_launch(void* const* d_in, const int* in_sizes, int n_in,
                              void* d_out, int out_size)
{
    const float* p      = (const float*)d_in[0];
    const float* x      = (const float*)d_in[1];
    const int*   idx    = (const int*)  d_in[2];
    const float* w1     = (const float*)d_in[3];
    const float* g1     = (const float*)d_in[4];
    const float* b1     = (const float*)d_in[5];
    const float* m1     = (const float*)d_in[6];
    const float* v1     = (const float*)d_in[7];
    const float* conv_w = (const float*)d_in[8];
    const float* g2     = (const float*)d_in[9];
    const float* b2     = (const float*)d_in[10];
    const float* m2     = (const float*)d_in[11];
    const float* v2     = (const float*)d_in[12];
    const float* w3     = (const float*)d_in[13];
    const float* g3     = (const float*)d_in[14];
    const float* b3     = (const float*)d_in[15];
    const float* m3     = (const float*)d_in[16];
    const float* v3     = (const float*)d_in[17];
    float* out = (float*)d_out;

    const int N = in_sizes[0] / 3;

    stage1_kernel<<<(N + 127) / 128, 256>>>(p, x, w1, g1, b1, m1, v1, conv_w, N);
    stage2_kernel<<<(N + 63) / 64, 256>>>(p, x, idx, conv_w,
                                          g2, b2, m2, v2, w3, g3, b3, m3, v3,
                                          out, N);
}